// round 3
// baseline (speedup 1.0000x reference)
#include <cuda_runtime.h>

#define BSZ 16
#define L 1024
#define HDIM 768
#define OUTW (4*HDIM)

// Scratch (device globals: allocation-free rule)
__device__ float g_xproj[(size_t)BSZ * L * HDIM];   // 50.3 MB
__device__ float g_yproj[(size_t)BSZ * L * HDIM];   // 50.3 MB
__device__ float g_scores[(size_t)BSZ * L * L];     // 67.1 MB

// ---------------------------------------------------------------------------
// Shared GEMM tile core: C(128x128) += A(128xK) * B(128xK)^T
// Both operands K-contiguous (row stride lda/ldb). BK=16, 256 threads,
// 8x8 accumulator per thread.
// ---------------------------------------------------------------------------
__device__ __forceinline__ void gemm_tile_nt(
    const float* __restrict__ Aptr, const float* __restrict__ Bptr,
    int K, int lda, int ldb,
    float (&As)[16][128], float (&Bs)[16][128], float (&acc)[8][8])
{
    const int tid  = threadIdx.x;
    const int lrow = tid >> 2;          // 0..63
    const int lk4  = (tid & 3) << 2;    // 0,4,8,12
    const int trow = (tid >> 4) << 3;   // 0..120 step 8
    const int tcol = (tid & 15) << 3;   // 0..120 step 8

    for (int kt = 0; kt < K; kt += 16) {
        const float* ap = Aptr + (size_t)lrow * lda + kt + lk4;
        const float* bp = Bptr + (size_t)lrow * ldb + kt + lk4;
        float4 a0 = *(const float4*)ap;
        float4 a1 = *(const float4*)(ap + (size_t)64 * lda);
        float4 b0 = *(const float4*)bp;
        float4 b1 = *(const float4*)(bp + (size_t)64 * ldb);
        __syncthreads();
        As[lk4+0][lrow]    = a0.x; As[lk4+1][lrow]    = a0.y;
        As[lk4+2][lrow]    = a0.z; As[lk4+3][lrow]    = a0.w;
        As[lk4+0][lrow+64] = a1.x; As[lk4+1][lrow+64] = a1.y;
        As[lk4+2][lrow+64] = a1.z; As[lk4+3][lrow+64] = a1.w;
        Bs[lk4+0][lrow]    = b0.x; Bs[lk4+1][lrow]    = b0.y;
        Bs[lk4+2][lrow]    = b0.z; Bs[lk4+3][lrow]    = b0.w;
        Bs[lk4+0][lrow+64] = b1.x; Bs[lk4+1][lrow+64] = b1.y;
        Bs[lk4+2][lrow+64] = b1.z; Bs[lk4+3][lrow+64] = b1.w;
        __syncthreads();
        #pragma unroll
        for (int k = 0; k < 16; ++k) {
            float ra[8], rb[8];
            *(float4*)(&ra[0]) = *(const float4*)(&As[k][trow]);
            *(float4*)(&ra[4]) = *(const float4*)(&As[k][trow + 4]);
            *(float4*)(&rb[0]) = *(const float4*)(&Bs[k][tcol]);
            *(float4*)(&rb[4]) = *(const float4*)(&Bs[k][tcol + 4]);
            #pragma unroll
            for (int i = 0; i < 8; ++i)
                #pragma unroll
                for (int j = 0; j < 8; ++j)
                    acc[i][j] += ra[i] * rb[j];
        }
    }
}

// ---------------------------------------------------------------------------
// Kernel 1: projection  proj = relu(X @ W^T + b)
// grid (6, M/128) ; which: 0 -> g_xproj, 1 -> g_yproj
// ---------------------------------------------------------------------------
__global__ __launch_bounds__(256, 2)
void proj_kernel(const float* __restrict__ X, const float* __restrict__ W,
                 const float* __restrict__ bias, int which)
{
    __shared__ float As[16][128];
    __shared__ float Bs[16][128];
    float acc[8][8] = {};

    const float* Aptr = X + (size_t)blockIdx.y * 128 * HDIM;
    const float* Bptr = W + (size_t)blockIdx.x * 128 * HDIM;
    gemm_tile_nt(Aptr, Bptr, HDIM, HDIM, HDIM, As, Bs, acc);

    float* out = which ? g_yproj : g_xproj;
    const int tid  = threadIdx.x;
    const int trow = (tid >> 4) << 3;
    const int tcol = (tid & 15) << 3;
    const int n0   = blockIdx.x * 128 + tcol;

    float4 bv0 = *(const float4*)(bias + n0);
    float4 bv1 = *(const float4*)(bias + n0 + 4);

    float* Cp = out + ((size_t)blockIdx.y * 128 + trow) * HDIM + n0;
    #pragma unroll
    for (int i = 0; i < 8; ++i) {
        float4 o0, o1;
        o0.x = fmaxf(acc[i][0] + bv0.x, 0.f);
        o0.y = fmaxf(acc[i][1] + bv0.y, 0.f);
        o0.z = fmaxf(acc[i][2] + bv0.z, 0.f);
        o0.w = fmaxf(acc[i][3] + bv0.w, 0.f);
        o1.x = fmaxf(acc[i][4] + bv1.x, 0.f);
        o1.y = fmaxf(acc[i][5] + bv1.y, 0.f);
        o1.z = fmaxf(acc[i][6] + bv1.z, 0.f);
        o1.w = fmaxf(acc[i][7] + bv1.w, 0.f);
        *(float4*)(Cp + (size_t)i * HDIM)     = o0;
        *(float4*)(Cp + (size_t)i * HDIM + 4) = o1;
    }
}

// ---------------------------------------------------------------------------
// Kernel 2: scores[b,i,j] = xproj[b,i,:] . yproj[b,j,:], masked -inf
// x2_mask is int32 (harness marshals bool -> int32). nonzero => masked.
// grid (8, 8, 16)
// ---------------------------------------------------------------------------
__global__ __launch_bounds__(256, 2)
void scores_kernel(const int* __restrict__ x2_mask)
{
    __shared__ float As[16][128];
    __shared__ float Bs[16][128];
    float acc[8][8] = {};

    const int z = blockIdx.z;
    const float* Aptr = g_xproj + (size_t)z * L * HDIM + (size_t)blockIdx.y * 128 * HDIM;
    const float* Bptr = g_yproj + (size_t)z * L * HDIM + (size_t)blockIdx.x * 128 * HDIM;
    gemm_tile_nt(Aptr, Bptr, HDIM, HDIM, HDIM, As, Bs, acc);

    const int tid  = threadIdx.x;
    const int trow = (tid >> 4) << 3;
    const int tcol = (tid & 15) << 3;
    const int m0   = blockIdx.y * 128 + trow;
    const int n0   = blockIdx.x * 128 + tcol;

    const float NEGINF = __int_as_float(0xff800000u);
    const int* mp = x2_mask + (size_t)z * L + n0;
    int msk[8];
    #pragma unroll
    for (int j = 0; j < 8; ++j) msk[j] = mp[j];

    float* Cp = g_scores + (size_t)z * L * L + (size_t)m0 * L + n0;
    #pragma unroll
    for (int i = 0; i < 8; ++i) {
        float4 o0, o1;
        o0.x = msk[0] ? NEGINF : acc[i][0];
        o0.y = msk[1] ? NEGINF : acc[i][1];
        o0.z = msk[2] ? NEGINF : acc[i][2];
        o0.w = msk[3] ? NEGINF : acc[i][3];
        o1.x = msk[4] ? NEGINF : acc[i][4];
        o1.y = msk[5] ? NEGINF : acc[i][5];
        o1.z = msk[6] ? NEGINF : acc[i][6];
        o1.w = msk[7] ? NEGINF : acc[i][7];
        *(float4*)(Cp + (size_t)i * L)     = o0;
        *(float4*)(Cp + (size_t)i * L + 4) = o1;
    }
}

// ---------------------------------------------------------------------------
// Kernel 3: in-place row softmax over 1024 cols. grid(16384), 256 threads.
// ---------------------------------------------------------------------------
__global__ __launch_bounds__(256)
void softmax_kernel()
{
    const int tid = threadIdx.x;
    float4* p = ((float4*)g_scores) + (size_t)blockIdx.x * (L / 4) + tid;
    float4 v = *p;

    __shared__ float smax[8];
    __shared__ float ssum[8];

    float m = fmaxf(fmaxf(v.x, v.y), fmaxf(v.z, v.w));
    #pragma unroll
    for (int o = 16; o > 0; o >>= 1)
        m = fmaxf(m, __shfl_xor_sync(0xffffffffu, m, o));
    if ((tid & 31) == 0) smax[tid >> 5] = m;
    __syncthreads();
    m = smax[0];
    #pragma unroll
    for (int w = 1; w < 8; ++w) m = fmaxf(m, smax[w]);

    float4 e;
    e.x = expf(v.x - m); e.y = expf(v.y - m);
    e.z = expf(v.z - m); e.w = expf(v.w - m);
    float s = (e.x + e.y) + (e.z + e.w);
    #pragma unroll
    for (int o = 16; o > 0; o >>= 1)
        s += __shfl_xor_sync(0xffffffffu, s, o);
    if ((tid & 31) == 0) ssum[tid >> 5] = s;
    __syncthreads();
    s = 0.f;
    #pragma unroll
    for (int w = 0; w < 8; ++w) s += ssum[w];

    const float inv = 1.0f / s;
    e.x *= inv; e.y *= inv; e.z *= inv; e.w *= inv;
    *p = e;
}

// ---------------------------------------------------------------------------
// Kernel 4: att = alpha @ x2 (NN gemm, K=1024) + concat epilogue
// out[b,i,:] = [x1, att, x1*att, x1-att]. grid (6, 8, 16)
// ---------------------------------------------------------------------------
__global__ __launch_bounds__(256, 2)
void att_kernel(const float* __restrict__ x1, const float* __restrict__ x2,
                float* __restrict__ out)
{
    __shared__ float As[16][128];
    __shared__ float Bs[16][128];
    float acc[8][8] = {};

    const int z   = blockIdx.z;
    const int tid = threadIdx.x;
    const int lrow = tid >> 2;          // A loader: 0..63
    const int lk4  = (tid & 3) << 2;
    const int bkr  = tid >> 5;          // B loader: k row 0..7
    const int bn4  = (tid & 31) << 2;   // n col *4
    const int trow = (tid >> 4) << 3;
    const int tcol = (tid & 15) << 3;

    const float* Aptr  = g_scores + (size_t)z * L * L + (size_t)blockIdx.y * 128 * L;
    const float* Bbase = x2 + (size_t)z * L * HDIM + blockIdx.x * 128;

    for (int kt = 0; kt < L; kt += 16) {
        const float* ap = Aptr + (size_t)lrow * L + kt + lk4;
        float4 a0 = *(const float4*)ap;
        float4 a1 = *(const float4*)(ap + (size_t)64 * L);
        float4 b0 = *(const float4*)(Bbase + (size_t)(kt + bkr)     * HDIM + bn4);
        float4 b1 = *(const float4*)(Bbase + (size_t)(kt + bkr + 8) * HDIM + bn4);
        __syncthreads();
        As[lk4+0][lrow]    = a0.x; As[lk4+1][lrow]    = a0.y;
        As[lk4+2][lrow]    = a0.z; As[lk4+3][lrow]    = a0.w;
        As[lk4+0][lrow+64] = a1.x; As[lk4+1][lrow+64] = a1.y;
        As[lk4+2][lrow+64] = a1.z; As[lk4+3][lrow+64] = a1.w;
        *(float4*)(&Bs[bkr][bn4])     = b0;
        *(float4*)(&Bs[bkr + 8][bn4]) = b1;
        __syncthreads();
        #pragma unroll
        for (int k = 0; k < 16; ++k) {
            float ra[8], rb[8];
            *(float4*)(&ra[0]) = *(const float4*)(&As[k][trow]);
            *(float4*)(&ra[4]) = *(const float4*)(&As[k][trow + 4]);
            *(float4*)(&rb[0]) = *(const float4*)(&Bs[k][tcol]);
            *(float4*)(&rb[4]) = *(const float4*)(&Bs[k][tcol + 4]);
            #pragma unroll
            for (int i = 0; i < 8; ++i)
                #pragma unroll
                for (int j = 0; j < 8; ++j)
                    acc[i][j] += ra[i] * rb[j];
        }
    }

    const int m0 = blockIdx.y * 128 + trow;
    const int n0 = blockIdx.x * 128 + tcol;
    #pragma unroll
    for (int i = 0; i < 8; ++i) {
        const float* xp = x1 + ((size_t)z * L + m0 + i) * HDIM + n0;
        float4 xv0 = *(const float4*)xp;
        float4 xv1 = *(const float4*)(xp + 4);
        float4 A0 = make_float4(acc[i][0], acc[i][1], acc[i][2], acc[i][3]);
        float4 A1 = make_float4(acc[i][4], acc[i][5], acc[i][6], acc[i][7]);
        float* op = out + ((size_t)z * L + m0 + i) * OUTW + n0;
        // chunk 0: x1
        *(float4*)(op)                = xv0;
        *(float4*)(op + 4)            = xv1;
        // chunk 1: att
        *(float4*)(op + HDIM)         = A0;
        *(float4*)(op + HDIM + 4)     = A1;
        // chunk 2: x1 * att
        float4 p0 = make_float4(xv0.x * A0.x, xv0.y * A0.y, xv0.z * A0.z, xv0.w * A0.w);
        float4 p1 = make_float4(xv1.x * A1.x, xv1.y * A1.y, xv1.z * A1.z, xv1.w * A1.w);
        *(float4*)(op + 2 * HDIM)     = p0;
        *(float4*)(op + 2 * HDIM + 4) = p1;
        // chunk 3: x1 - att
        float4 d0 = make_float4(xv0.x - A0.x, xv0.y - A0.y, xv0.z - A0.z, xv0.w - A0.w);
        float4 d1 = make_float4(xv1.x - A1.x, xv1.y - A1.y, xv1.z - A1.z, xv1.w - A1.w);
        *(float4*)(op + 3 * HDIM)     = d0;
        *(float4*)(op + 3 * HDIM + 4) = d1;
    }
}

// ---------------------------------------------------------------------------
extern "C" void kernel_launch(void* const* d_in, const int* in_sizes, int n_in,
                              void* d_out, int out_size)
{
    const float* x1 = (const float*)d_in[0];
    const float* x2 = (const float*)d_in[1];
    // d_in[2] = x1_mask (unused by reference)
    const int* x2_mask = (const int*)d_in[3];
    const float* W    = (const float*)d_in[4];
    const float* bias = (const float*)d_in[5];
    float* out = (float*)d_out;

    dim3 blk(256);
    proj_kernel<<<dim3(HDIM / 128, (BSZ * L) / 128), blk>>>(x1, W, bias, 0);
    proj_kernel<<<dim3(HDIM / 128, (BSZ * L) / 128), blk>>>(x2, W, bias, 1);
    scores_kernel<<<dim3(L / 128, L / 128, BSZ), blk>>>(x2_mask);
    softmax_kernel<<<dim3(BSZ * L), blk>>>();
    att_kernel<<<dim3(HDIM / 128, L / 128, BSZ), blk>>>(x1, x2, out);
}

// round 5
// speedup vs baseline: 1.8765x; 1.8765x over previous
#include <cuda_runtime.h>
#include <cuda_bf16.h>
#include <cstdint>

#define BSZ 16
#define L 1024
#define HDIM 768
#define OUTW (4*HDIM)

typedef __nv_bfloat16 bf16;

// ---------------- scratch (device globals; allocation-free rule) ------------
__device__ __align__(256) bf16 g_x1h[(size_t)BSZ*L*HDIM];
__device__ __align__(256) bf16 g_x1l[(size_t)BSZ*L*HDIM];
__device__ __align__(256) bf16 g_x2h[(size_t)BSZ*L*HDIM];
__device__ __align__(256) bf16 g_x2l[(size_t)BSZ*L*HDIM];
__device__ __align__(256) bf16 g_Wh [(size_t)HDIM*HDIM];
__device__ __align__(256) bf16 g_Wl [(size_t)HDIM*HDIM];
__device__ __align__(256) bf16 g_xph[(size_t)BSZ*L*HDIM];
__device__ __align__(256) bf16 g_xpl[(size_t)BSZ*L*HDIM];
__device__ __align__(256) bf16 g_yph[(size_t)BSZ*L*HDIM];
__device__ __align__(256) bf16 g_ypl[(size_t)BSZ*L*HDIM];
__device__ __align__(256) bf16 g_x2Th[(size_t)BSZ*HDIM*L];
__device__ __align__(256) bf16 g_x2Tl[(size_t)BSZ*HDIM*L];
__device__ __align__(256) bf16 g_ah [(size_t)BSZ*L*L];
__device__ __align__(256) bf16 g_al [(size_t)BSZ*L*L];
__device__ float g_scores[(size_t)BSZ*L*L];

// ---------------- helpers ---------------------------------------------------
__device__ __forceinline__ uint32_t smem_u32(const void* p) {
    uint32_t a;
    asm("{ .reg .u64 t; cvta.to.shared.u64 t, %1; cvt.u32.u64 %0, t; }"
        : "=r"(a) : "l"(p));
    return a;
}
__device__ __forceinline__ void cp16(uint32_t dst, const void* src) {
    asm volatile("cp.async.cg.shared.global [%0], [%1], 16;"
                 :: "r"(dst), "l"(src) : "memory");
}
__device__ __forceinline__ void ldmx4(uint32_t (&r)[4], uint32_t addr) {
    asm volatile("ldmatrix.sync.aligned.m8n8.x4.shared.b16 {%0,%1,%2,%3}, [%4];"
                 : "=r"(r[0]), "=r"(r[1]), "=r"(r[2]), "=r"(r[3]) : "r"(addr));
}
__device__ __forceinline__ void mma16816(float (&c)[4], const uint32_t (&a)[4],
                                         uint32_t b0, uint32_t b1) {
    asm volatile(
        "mma.sync.aligned.m16n8k16.row.col.f32.bf16.bf16.f32 "
        "{%0,%1,%2,%3}, {%4,%5,%6,%7}, {%8,%9}, {%0,%1,%2,%3};"
        : "+f"(c[0]), "+f"(c[1]), "+f"(c[2]), "+f"(c[3])
        : "r"(a[0]), "r"(a[1]), "r"(a[2]), "r"(a[3]), "r"(b0), "r"(b1));
}
__device__ __forceinline__ uint32_t pack_bf(bf16 a, bf16 b) {
    uint16_t ua = *(uint16_t*)&a, ub = *(uint16_t*)&b;
    return (uint32_t)ua | ((uint32_t)ub << 16);
}
__device__ __forceinline__ void split1(float f, bf16& h, bf16& l) {
    h = __float2bfloat16(f);
    l = __float2bfloat16(f - __bfloat162float(h));
}

// smem tile: 128 rows x 80B (64B data + 16B pad -> conflict-free ldmatrix)
#define ROWB 80
#define TILEB (128 * ROWB)          // 10240
#define BUFB  (2 * TILEB)           // A+B per stage
#define SMEMB (2 * BUFB)            // double buffer = 40960

// ---------------------------------------------------------------------------
// Split-bf16 3-pass mainloop: acc(64x32 per warp of 128x128 CTA tile) =
//   Ah.Bh^T + Ah.Bl^T + Al.Bh^T, BK=32, cp.async double-buffered.
// ---------------------------------------------------------------------------
__device__ __forceinline__ void gemm_core(
    const bf16* __restrict__ Ah, const bf16* __restrict__ Al, int lda,
    const bf16* __restrict__ Bh, const bf16* __restrict__ Bl, int ldb,
    int K, char* smem, float (&acc)[4][4][4])
{
    const int tid  = threadIdx.x;
    const int lane = tid & 31;
    const int wid  = tid >> 5;
    const int wm   = (wid & 1) * 64;
    const int wn   = (wid >> 1) * 32;
    const uint32_t sbase = smem_u32(smem);

    const int nk = K >> 5;
    const int total = 3 * nk;

    const int ra = tid >> 2, ca = tid & 3;              // j = tid
    const int rb = (tid + 256) >> 2;                    // j = tid + 256

    for (int i = -1; i < total; ++i) {
        // issue chunk i+1
        if (i + 1 < total) {
            const int chunk = i + 1;
            const int pass = chunk / nk;
            const int kt = (chunk % nk) << 5;
            const bf16* Ap = (pass == 2) ? Al : Ah;
            const bf16* Bp = (pass == 1) ? Bl : Bh;
            const uint32_t dA = sbase + (chunk & 1) * BUFB;
            const uint32_t dB = dA + TILEB;
            cp16(dA + ra * ROWB + ca * 16, Ap + (size_t)ra * lda + kt + ca * 8);
            cp16(dA + rb * ROWB + ca * 16, Ap + (size_t)rb * lda + kt + ca * 8);
            cp16(dB + ra * ROWB + ca * 16, Bp + (size_t)ra * ldb + kt + ca * 8);
            cp16(dB + rb * ROWB + ca * 16, Bp + (size_t)rb * ldb + kt + ca * 8);
            asm volatile("cp.async.commit_group;" ::: "memory");
        }
        if (i < 0) continue;
        if (i + 1 < total)
            asm volatile("cp.async.wait_group 1;" ::: "memory");
        else
            asm volatile("cp.async.wait_group 0;" ::: "memory");
        __syncthreads();

        const uint32_t sA = sbase + (i & 1) * BUFB;
        const uint32_t sB = sA + TILEB;
        #pragma unroll
        for (int kh = 0; kh < 2; ++kh) {
            const uint32_t coff = (uint32_t)(kh * 2 + (lane >> 4)) * 16;
            uint32_t bb0[4], bb1[4];
            {
                uint32_t addr = sB + (uint32_t)(wn + (lane & 15)) * ROWB + coff;
                ldmx4(bb0, addr);
                ldmx4(bb1, addr + 16u * ROWB);
            }
            #pragma unroll
            for (int mi = 0; mi < 4; ++mi) {
                uint32_t aa[4];
                ldmx4(aa, sA + (uint32_t)(wm + mi * 16 + (lane & 15)) * ROWB + coff);
                mma16816(acc[mi][0], aa, bb0[0], bb0[2]);
                mma16816(acc[mi][1], aa, bb0[1], bb0[3]);
                mma16816(acc[mi][2], aa, bb1[0], bb1[2]);
                mma16816(acc[mi][3], aa, bb1[1], bb1[3]);
            }
        }
        __syncthreads();
    }
}

// ---------------------------------------------------------------------------
// Split kernels
// ---------------------------------------------------------------------------
__global__ __launch_bounds__(256) void split_kernel(const float* __restrict__ in,
                                                    int which, int n4)
{
    bf16 *hi, *lo;
    if (which == 0)      { hi = g_x1h; lo = g_x1l; }
    else if (which == 1) { hi = g_x2h; lo = g_x2l; }
    else                 { hi = g_Wh;  lo = g_Wl;  }
    int i = blockIdx.x * 256 + threadIdx.x;
    if (i >= n4) return;
    float4 v = ((const float4*)in)[i];
    bf16 h0, h1, h2, h3, l0, l1, l2, l3;
    split1(v.x, h0, l0); split1(v.y, h1, l1);
    split1(v.z, h2, l2); split1(v.w, h3, l3);
    ((uint2*)hi)[i] = make_uint2(pack_bf(h0, h1), pack_bf(h2, h3));
    ((uint2*)lo)[i] = make_uint2(pack_bf(l0, l1), pack_bf(l2, l3));
}

__global__ __launch_bounds__(256) void transpose_split_kernel(const float* __restrict__ x2)
{
    __shared__ float t[32][33];
    const int b = blockIdx.z;
    const int h0 = blockIdx.x * 32, l0 = blockIdx.y * 32;
    const int tx = threadIdx.x & 31, ty = threadIdx.x >> 5;   // ty 0..7
    const float* src = x2 + ((size_t)b * L + l0) * HDIM + h0;
    #pragma unroll
    for (int j = 0; j < 4; ++j)
        t[ty + j * 8][tx] = src[(size_t)(ty + j * 8) * HDIM + tx];
    __syncthreads();
    #pragma unroll
    for (int j = 0; j < 4; ++j) {
        int r = ty + j * 8;                                   // h-local
        float v = t[tx][r];
        bf16 h, l; split1(v, h, l);
        size_t o = ((size_t)b * HDIM + h0 + r) * L + l0 + tx;
        g_x2Th[o] = h;
        g_x2Tl[o] = l;
    }
}

// ---------------------------------------------------------------------------
// GEMM 1: proj = relu(X @ W^T + b) -> bf16 hi/lo.  grid (6, 128)
// ---------------------------------------------------------------------------
__global__ __launch_bounds__(256) void gemm_proj(const float* __restrict__ bias, int which)
{
    __shared__ __align__(128) char gsm[SMEMB];
    float acc[4][4][4] = {};

    const bf16* Ah = which ? g_x2h : g_x1h;
    const bf16* Al = which ? g_x2l : g_x1l;
    bf16* Oh = which ? g_yph : g_xph;
    bf16* Ol = which ? g_ypl : g_xpl;
    const size_t m0 = (size_t)blockIdx.y * 128;
    const int n0 = blockIdx.x * 128;

    gemm_core(Ah + m0 * HDIM, Al + m0 * HDIM, HDIM,
              g_Wh + (size_t)n0 * HDIM, g_Wl + (size_t)n0 * HDIM, HDIM,
              HDIM, gsm, acc);

    const int tid = threadIdx.x, lane = tid & 31, wid = tid >> 5;
    const int wm = (wid & 1) * 64, wn = (wid >> 1) * 32;
    #pragma unroll
    for (int mi = 0; mi < 4; ++mi)
        #pragma unroll
        for (int ni = 0; ni < 4; ++ni)
            #pragma unroll
            for (int h = 0; h < 2; ++h) {
                const size_t m = m0 + wm + mi * 16 + (lane >> 2) + h * 8;
                const int n = n0 + wn + ni * 8 + (lane & 3) * 2;
                float f0 = fmaxf(acc[mi][ni][h * 2]     + bias[n],     0.f);
                float f1 = fmaxf(acc[mi][ni][h * 2 + 1] + bias[n + 1], 0.f);
                bf16 h0, l0, h1, l1;
                split1(f0, h0, l0); split1(f1, h1, l1);
                *(uint32_t*)(Oh + m * HDIM + n) = pack_bf(h0, h1);
                *(uint32_t*)(Ol + m * HDIM + n) = pack_bf(l0, l1);
            }
}

// ---------------------------------------------------------------------------
// GEMM 2: scores = xproj . yproj^T, -inf mask -> fp32.  grid (8, 8, 16)
// ---------------------------------------------------------------------------
__global__ __launch_bounds__(256) void gemm_scores(const int* __restrict__ x2_mask)
{
    __shared__ __align__(128) char gsm[SMEMB];
    float acc[4][4][4] = {};

    const int b = blockIdx.z;
    const size_t m0 = (size_t)blockIdx.y * 128;
    const int n0 = blockIdx.x * 128;
    const size_t boff = (size_t)b * L * HDIM;

    gemm_core(g_xph + boff + m0 * HDIM, g_xpl + boff + m0 * HDIM, HDIM,
              g_yph + boff + (size_t)n0 * HDIM, g_ypl + boff + (size_t)n0 * HDIM, HDIM,
              HDIM, gsm, acc);

    const int tid = threadIdx.x, lane = tid & 31, wid = tid >> 5;
    const int wm = (wid & 1) * 64, wn = (wid >> 1) * 32;
    const float NEGINF = __int_as_float(0xff800000u);
    const int* mrow = x2_mask + (size_t)b * L + n0;
    #pragma unroll
    for (int mi = 0; mi < 4; ++mi)
        #pragma unroll
        for (int ni = 0; ni < 4; ++ni)
            #pragma unroll
            for (int h = 0; h < 2; ++h) {
                const size_t m = m0 + wm + mi * 16 + (lane >> 2) + h * 8;
                const int n = wn + ni * 8 + (lane & 3) * 2;
                float2 o;
                o.x = mrow[n]     ? NEGINF : acc[mi][ni][h * 2];
                o.y = mrow[n + 1] ? NEGINF : acc[mi][ni][h * 2 + 1];
                *(float2*)(g_scores + ((size_t)b * L + m) * L + n0 + n) = o;
            }
}

// ---------------------------------------------------------------------------
// Softmax: fp32 scores in, bf16 hi/lo alpha out. grid(16384), 256 threads.
// ---------------------------------------------------------------------------
__global__ __launch_bounds__(256) void softmax_kernel()
{
    const int tid = threadIdx.x;
    const size_t row = blockIdx.x;
    const float4* p = ((const float4*)g_scores) + row * (L / 4) + tid;
    float4 v = *p;

    __shared__ float smax[8];
    __shared__ float ssum[8];

    float m = fmaxf(fmaxf(v.x, v.y), fmaxf(v.z, v.w));
    #pragma unroll
    for (int o = 16; o > 0; o >>= 1)
        m = fmaxf(m, __shfl_xor_sync(0xffffffffu, m, o));
    if ((tid & 31) == 0) smax[tid >> 5] = m;
    __syncthreads();
    m = smax[0];
    #pragma unroll
    for (int w = 1; w < 8; ++w) m = fmaxf(m, smax[w]);

    float4 e;
    e.x = expf(v.x - m); e.y = expf(v.y - m);
    e.z = expf(v.z - m); e.w = expf(v.w - m);
    float s = (e.x + e.y) + (e.z + e.w);
    #pragma unroll
    for (int o = 16; o > 0; o >>= 1)
        s += __shfl_xor_sync(0xffffffffu, s, o);
    if ((tid & 31) == 0) ssum[tid >> 5] = s;
    __syncthreads();
    s = 0.f;
    #pragma unroll
    for (int w = 0; w < 8; ++w) s += ssum[w];

    const float inv = 1.0f / s;
    e.x *= inv; e.y *= inv; e.z *= inv; e.w *= inv;

    bf16 h0, h1, h2, h3, l0, l1, l2, l3;
    split1(e.x, h0, l0); split1(e.y, h1, l1);
    split1(e.z, h2, l2); split1(e.w, h3, l3);
    *(uint2*)(g_ah + row * L + tid * 4) = make_uint2(pack_bf(h0, h1), pack_bf(h2, h3));
    *(uint2*)(g_al + row * L + tid * 4) = make_uint2(pack_bf(l0, l1), pack_bf(l2, l3));
}

// ---------------------------------------------------------------------------
// GEMM 3: att = alpha @ x2 (+ concat epilogue). grid (6, 8, 16)
// ---------------------------------------------------------------------------
__global__ __launch_bounds__(256) void gemm_att(const float* __restrict__ x1,
                                                float* __restrict__ out)
{
    __shared__ __align__(128) char gsm[SMEMB];
    float acc[4][4][4] = {};

    const int b = blockIdx.z;
    const size_t m0 = (size_t)blockIdx.y * 128;
    const int n0 = blockIdx.x * 128;

    gemm_core(g_ah + ((size_t)b * L + m0) * L, g_al + ((size_t)b * L + m0) * L, L,
              g_x2Th + ((size_t)b * HDIM + n0) * L, g_x2Tl + ((size_t)b * HDIM + n0) * L, L,
              L, gsm, acc);

    const int tid = threadIdx.x, lane = tid & 31, wid = tid >> 5;
    const int wm = (wid & 1) * 64, wn = (wid >> 1) * 32;
    #pragma unroll
    for (int mi = 0; mi < 4; ++mi)
        #pragma unroll
        for (int ni = 0; ni < 4; ++ni)
            #pragma unroll
            for (int h = 0; h < 2; ++h) {
                const size_t m = m0 + wm + mi * 16 + (lane >> 2) + h * 8;
                const int n = n0 + wn + ni * 8 + (lane & 3) * 2;
                float2 A;
                A.x = acc[mi][ni][h * 2];
                A.y = acc[mi][ni][h * 2 + 1];
                const float* xp = x1 + ((size_t)b * L + m) * HDIM + n;
                float2 xv = *(const float2*)xp;
                float* op = out + ((size_t)b * L + m) * OUTW + n;
                *(float2*)(op)            = xv;
                *(float2*)(op + HDIM)     = A;
                *(float2*)(op + 2 * HDIM) = make_float2(xv.x * A.x, xv.y * A.y);
                *(float2*)(op + 3 * HDIM) = make_float2(xv.x - A.x, xv.y - A.y);
            }
}

// ---------------------------------------------------------------------------
extern "C" void kernel_launch(void* const* d_in, const int* in_sizes, int n_in,
                              void* d_out, int out_size)
{
    const float* x1 = (const float*)d_in[0];
    const float* x2 = (const float*)d_in[1];
    // d_in[2] = x1_mask (unused by reference)
    const int* x2_mask = (const int*)d_in[3];
    const float* W    = (const float*)d_in[4];
    const float* bias = (const float*)d_in[5];
    float* out = (float*)d_out;

    const int n4x = BSZ * L * HDIM / 4;   // 3,145,728
    const int n4w = HDIM * HDIM / 4;      // 147,456

    split_kernel<<<n4x / 256, 256>>>(x1, 0, n4x);
    split_kernel<<<n4x / 256, 256>>>(x2, 1, n4x);
    split_kernel<<<n4w / 256, 256>>>(W, 2, n4w);
    transpose_split_kernel<<<dim3(HDIM / 32, L / 32, BSZ), 256>>>(x2);

    gemm_proj<<<dim3(HDIM / 128, (BSZ * L) / 128), 256>>>(bias, 0);
    gemm_proj<<<dim3(HDIM / 128, (BSZ * L) / 128), 256>>>(bias, 1);
    gemm_scores<<<dim3(L / 128, L / 128, BSZ), 256>>>(x2_mask);
    softmax_kernel<<<BSZ * L, 256>>>();
    gemm_att<<<dim3(HDIM / 128, L / 128, BSZ), 256>>>(x1, out);
}

// round 6
// speedup vs baseline: 2.1818x; 1.1627x over previous
#include <cuda_runtime.h>
#include <cuda_bf16.h>
#include <cstdint>

#define BSZ 16
#define L 1024
#define HDIM 768
#define OUTW (4*HDIM)

typedef __nv_bfloat16 bf16;

// ---------------- scratch (device globals; allocation-free rule) ------------
__device__ __align__(256) bf16 g_x1h[(size_t)BSZ*L*HDIM];
__device__ __align__(256) bf16 g_x1l[(size_t)BSZ*L*HDIM];
__device__ __align__(256) bf16 g_x2h[(size_t)BSZ*L*HDIM];
__device__ __align__(256) bf16 g_x2l[(size_t)BSZ*L*HDIM];
__device__ __align__(256) bf16 g_Wh [(size_t)HDIM*HDIM];
__device__ __align__(256) bf16 g_Wl [(size_t)HDIM*HDIM];
__device__ __align__(256) bf16 g_xph[(size_t)BSZ*L*HDIM];
__device__ __align__(256) bf16 g_xpl[(size_t)BSZ*L*HDIM];
__device__ __align__(256) bf16 g_yph[(size_t)BSZ*L*HDIM];
__device__ __align__(256) bf16 g_ypl[(size_t)BSZ*L*HDIM];
__device__ __align__(256) bf16 g_x2Th[(size_t)BSZ*HDIM*L];
__device__ __align__(256) bf16 g_x2Tl[(size_t)BSZ*HDIM*L];
__device__ __align__(256) bf16 g_ah [(size_t)BSZ*L*L];
__device__ __align__(256) bf16 g_al [(size_t)BSZ*L*L];
__device__ float g_scores[(size_t)BSZ*L*L];

// ---------------- helpers ---------------------------------------------------
__device__ __forceinline__ uint32_t smem_u32(const void* p) {
    uint32_t a;
    asm("{ .reg .u64 t; cvta.to.shared.u64 t, %1; cvt.u32.u64 %0, t; }"
        : "=r"(a) : "l"(p));
    return a;
}
__device__ __forceinline__ void cp16(uint32_t dst, const void* src) {
    asm volatile("cp.async.cg.shared.global [%0], [%1], 16;"
                 :: "r"(dst), "l"(src) : "memory");
}
__device__ __forceinline__ void ldmx4(uint32_t (&r)[4], uint32_t addr) {
    asm volatile("ldmatrix.sync.aligned.m8n8.x4.shared.b16 {%0,%1,%2,%3}, [%4];"
                 : "=r"(r[0]), "=r"(r[1]), "=r"(r[2]), "=r"(r[3]) : "r"(addr));
}
__device__ __forceinline__ void mma16816(float (&c)[4], const uint32_t (&a)[4],
                                         uint32_t b0, uint32_t b1) {
    asm volatile(
        "mma.sync.aligned.m16n8k16.row.col.f32.bf16.bf16.f32 "
        "{%0,%1,%2,%3}, {%4,%5,%6,%7}, {%8,%9}, {%0,%1,%2,%3};"
        : "+f"(c[0]), "+f"(c[1]), "+f"(c[2]), "+f"(c[3])
        : "r"(a[0]), "r"(a[1]), "r"(a[2]), "r"(a[3]), "r"(b0), "r"(b1));
}
__device__ __forceinline__ uint32_t pack_bf(bf16 a, bf16 b) {
    uint16_t ua = *(uint16_t*)&a, ub = *(uint16_t*)&b;
    return (uint32_t)ua | ((uint32_t)ub << 16);
}
__device__ __forceinline__ void split1(float f, bf16& h, bf16& l) {
    h = __float2bfloat16(f);
    l = __float2bfloat16(f - __bfloat162float(h));
}

// smem tile: 128 rows x 80B (64B data + 16B pad -> conflict-free ldmatrix)
#define ROWB 80
#define TILEB (128 * ROWB)          // 10240
#define STAGEB (4 * TILEB)          // Ah,Al,Bh,Bl per stage = 40960
#define SMEMB (2 * STAGEB)          // double buffer = 81920

// ---------------------------------------------------------------------------
// Fused split-bf16 mainloop: acc(64x32 per warp of 128x128 CTA tile) =
//   Ah.Bh^T + Ah.Bl^T + Al.Bh^T. Per K-chunk (BK=32) all 4 tiles staged once,
//   3 MMA contributions per fragment. cp.async double-buffered.
// ---------------------------------------------------------------------------
__device__ __forceinline__ void gemm_core(
    const bf16* __restrict__ Ah, const bf16* __restrict__ Al, int lda,
    const bf16* __restrict__ Bh, const bf16* __restrict__ Bl, int ldb,
    int K, char* smem, float (&acc)[4][4][4])
{
    const int tid  = threadIdx.x;
    const int lane = tid & 31;
    const int wid  = tid >> 5;
    const int wm   = (wid & 1) * 64;
    const int wn   = (wid >> 1) * 32;
    const uint32_t sbase = smem_u32(smem);
    const int nk = K >> 5;

    const int ra = tid >> 2, ca = tid & 3;
    const int rb = ra + 64;

    for (int i = -1; i < nk; ++i) {
        // stage chunk i+1 (all 4 tiles)
        if (i + 1 < nk) {
            const int kt = (i + 1) << 5;
            const uint32_t st = sbase + ((i + 1) & 1) * STAGEB;
            const uint32_t o0 = ra * ROWB + ca * 16;
            const uint32_t o1 = rb * ROWB + ca * 16;
            cp16(st + o0,             Ah + (size_t)ra * lda + kt + ca * 8);
            cp16(st + o1,             Ah + (size_t)rb * lda + kt + ca * 8);
            cp16(st + TILEB + o0,     Al + (size_t)ra * lda + kt + ca * 8);
            cp16(st + TILEB + o1,     Al + (size_t)rb * lda + kt + ca * 8);
            cp16(st + 2*TILEB + o0,   Bh + (size_t)ra * ldb + kt + ca * 8);
            cp16(st + 2*TILEB + o1,   Bh + (size_t)rb * ldb + kt + ca * 8);
            cp16(st + 3*TILEB + o0,   Bl + (size_t)ra * ldb + kt + ca * 8);
            cp16(st + 3*TILEB + o1,   Bl + (size_t)rb * ldb + kt + ca * 8);
            asm volatile("cp.async.commit_group;" ::: "memory");
        }
        if (i < 0) continue;
        if (i + 1 < nk)
            asm volatile("cp.async.wait_group 1;" ::: "memory");
        else
            asm volatile("cp.async.wait_group 0;" ::: "memory");
        __syncthreads();

        const uint32_t sAh = sbase + (i & 1) * STAGEB;
        const uint32_t sAl = sAh + TILEB;
        const uint32_t sBh = sAh + 2 * TILEB;
        const uint32_t sBl = sAh + 3 * TILEB;
        #pragma unroll
        for (int kh = 0; kh < 2; ++kh) {
            const uint32_t coff = (uint32_t)(kh * 2 + (lane >> 4)) * 16;
            const uint32_t brow = (uint32_t)(wn + (lane & 15)) * ROWB + coff;
            uint32_t bh0[4], bh1[4], bl0[4], bl1[4];
            ldmx4(bh0, sBh + brow);
            ldmx4(bh1, sBh + brow + 16u * ROWB);
            ldmx4(bl0, sBl + brow);
            ldmx4(bl1, sBl + brow + 16u * ROWB);
            #pragma unroll
            for (int mi = 0; mi < 4; ++mi) {
                const uint32_t arow = (uint32_t)(wm + mi * 16 + (lane & 15)) * ROWB + coff;
                uint32_t ah[4], al[4];
                ldmx4(ah, sAh + arow);
                ldmx4(al, sAl + arow);
                mma16816(acc[mi][0], ah, bh0[0], bh0[2]);
                mma16816(acc[mi][1], ah, bh0[1], bh0[3]);
                mma16816(acc[mi][2], ah, bh1[0], bh1[2]);
                mma16816(acc[mi][3], ah, bh1[1], bh1[3]);
                mma16816(acc[mi][0], ah, bl0[0], bl0[2]);
                mma16816(acc[mi][1], ah, bl0[1], bl0[3]);
                mma16816(acc[mi][2], ah, bl1[0], bl1[2]);
                mma16816(acc[mi][3], ah, bl1[1], bl1[3]);
                mma16816(acc[mi][0], al, bh0[0], bh0[2]);
                mma16816(acc[mi][1], al, bh0[1], bh0[3]);
                mma16816(acc[mi][2], al, bh1[0], bh1[2]);
                mma16816(acc[mi][3], al, bh1[1], bh1[3]);
            }
        }
        __syncthreads();
    }
}

// ---------------------------------------------------------------------------
// Split kernels
// ---------------------------------------------------------------------------
__global__ __launch_bounds__(256) void split_kernel(const float* __restrict__ in,
                                                    int which, int n4)
{
    bf16 *hi, *lo;
    if (which == 0)      { hi = g_x1h; lo = g_x1l; }
    else if (which == 1) { hi = g_x2h; lo = g_x2l; }
    else                 { hi = g_Wh;  lo = g_Wl;  }
    int i = blockIdx.x * 256 + threadIdx.x;
    if (i >= n4) return;
    float4 v = ((const float4*)in)[i];
    bf16 h0, h1, h2, h3, l0, l1, l2, l3;
    split1(v.x, h0, l0); split1(v.y, h1, l1);
    split1(v.z, h2, l2); split1(v.w, h3, l3);
    ((uint2*)hi)[i] = make_uint2(pack_bf(h0, h1), pack_bf(h2, h3));
    ((uint2*)lo)[i] = make_uint2(pack_bf(l0, l1), pack_bf(l2, l3));
}

__global__ __launch_bounds__(256) void transpose_split_kernel(const float* __restrict__ x2)
{
    __shared__ float t[32][33];
    const int b = blockIdx.z;
    const int h0 = blockIdx.x * 32, l0 = blockIdx.y * 32;
    const int tx = threadIdx.x & 31, ty = threadIdx.x >> 5;   // ty 0..7
    const float* src = x2 + ((size_t)b * L + l0) * HDIM + h0;
    #pragma unroll
    for (int j = 0; j < 4; ++j)
        t[ty + j * 8][tx] = src[(size_t)(ty + j * 8) * HDIM + tx];
    __syncthreads();
    #pragma unroll
    for (int j = 0; j < 4; ++j) {
        int r = ty + j * 8;                                   // h-local
        float v = t[tx][r];
        bf16 h, l; split1(v, h, l);
        size_t o = ((size_t)b * HDIM + h0 + r) * L + l0 + tx;
        g_x2Th[o] = h;
        g_x2Tl[o] = l;
    }
}

// ---------------------------------------------------------------------------
// GEMM 1: proj = relu(X @ W^T + b) -> bf16 hi/lo.  grid (6, 128)
// ---------------------------------------------------------------------------
__global__ __launch_bounds__(256, 2) void gemm_proj(const float* __restrict__ bias, int which)
{
    extern __shared__ __align__(128) char gsm[];
    float acc[4][4][4] = {};

    const bf16* Ah = which ? g_x2h : g_x1h;
    const bf16* Al = which ? g_x2l : g_x1l;
    bf16* Oh = which ? g_yph : g_xph;
    bf16* Ol = which ? g_ypl : g_xpl;
    const size_t m0 = (size_t)blockIdx.y * 128;
    const int n0 = blockIdx.x * 128;

    gemm_core(Ah + m0 * HDIM, Al + m0 * HDIM, HDIM,
              g_Wh + (size_t)n0 * HDIM, g_Wl + (size_t)n0 * HDIM, HDIM,
              HDIM, gsm, acc);

    const int tid = threadIdx.x, lane = tid & 31, wid = tid >> 5;
    const int wm = (wid & 1) * 64, wn = (wid >> 1) * 32;
    #pragma unroll
    for (int mi = 0; mi < 4; ++mi)
        #pragma unroll
        for (int ni = 0; ni < 4; ++ni)
            #pragma unroll
            for (int h = 0; h < 2; ++h) {
                const size_t m = m0 + wm + mi * 16 + (lane >> 2) + h * 8;
                const int n = n0 + wn + ni * 8 + (lane & 3) * 2;
                float f0 = fmaxf(acc[mi][ni][h * 2]     + bias[n],     0.f);
                float f1 = fmaxf(acc[mi][ni][h * 2 + 1] + bias[n + 1], 0.f);
                bf16 h0, l0, h1, l1;
                split1(f0, h0, l0); split1(f1, h1, l1);
                *(uint32_t*)(Oh + m * HDIM + n) = pack_bf(h0, h1);
                *(uint32_t*)(Ol + m * HDIM + n) = pack_bf(l0, l1);
            }
}

// ---------------------------------------------------------------------------
// GEMM 2: scores = xproj . yproj^T, -inf mask -> fp32.  grid (8, 8, 16)
// ---------------------------------------------------------------------------
__global__ __launch_bounds__(256, 2) void gemm_scores(const int* __restrict__ x2_mask)
{
    extern __shared__ __align__(128) char gsm[];
    float acc[4][4][4] = {};

    const int b = blockIdx.z;
    const size_t m0 = (size_t)blockIdx.y * 128;
    const int n0 = blockIdx.x * 128;
    const size_t boff = (size_t)b * L * HDIM;

    gemm_core(g_xph + boff + m0 * HDIM, g_xpl + boff + m0 * HDIM, HDIM,
              g_yph + boff + (size_t)n0 * HDIM, g_ypl + boff + (size_t)n0 * HDIM, HDIM,
              HDIM, gsm, acc);

    const int tid = threadIdx.x, lane = tid & 31, wid = tid >> 5;
    const int wm = (wid & 1) * 64, wn = (wid >> 1) * 32;
    const float NEGINF = __int_as_float(0xff800000u);
    const int* mrow = x2_mask + (size_t)b * L + n0;
    #pragma unroll
    for (int mi = 0; mi < 4; ++mi)
        #pragma unroll
        for (int ni = 0; ni < 4; ++ni)
            #pragma unroll
            for (int h = 0; h < 2; ++h) {
                const size_t m = m0 + wm + mi * 16 + (lane >> 2) + h * 8;
                const int n = wn + ni * 8 + (lane & 3) * 2;
                float2 o;
                o.x = mrow[n]     ? NEGINF : acc[mi][ni][h * 2];
                o.y = mrow[n + 1] ? NEGINF : acc[mi][ni][h * 2 + 1];
                *(float2*)(g_scores + ((size_t)b * L + m) * L + n0 + n) = o;
            }
}

// ---------------------------------------------------------------------------
// Softmax: fp32 scores in, bf16 hi/lo alpha out. grid(16384), 256 threads.
// ---------------------------------------------------------------------------
__global__ __launch_bounds__(256) void softmax_kernel()
{
    const int tid = threadIdx.x;
    const size_t row = blockIdx.x;
    const float4* p = ((const float4*)g_scores) + row * (L / 4) + tid;
    float4 v = *p;

    __shared__ float smax[8];
    __shared__ float ssum[8];

    float m = fmaxf(fmaxf(v.x, v.y), fmaxf(v.z, v.w));
    #pragma unroll
    for (int o = 16; o > 0; o >>= 1)
        m = fmaxf(m, __shfl_xor_sync(0xffffffffu, m, o));
    if ((tid & 31) == 0) smax[tid >> 5] = m;
    __syncthreads();
    m = smax[0];
    #pragma unroll
    for (int w = 1; w < 8; ++w) m = fmaxf(m, smax[w]);

    float4 e;
    e.x = expf(v.x - m); e.y = expf(v.y - m);
    e.z = expf(v.z - m); e.w = expf(v.w - m);
    float s = (e.x + e.y) + (e.z + e.w);
    #pragma unroll
    for (int o = 16; o > 0; o >>= 1)
        s += __shfl_xor_sync(0xffffffffu, s, o);
    if ((tid & 31) == 0) ssum[tid >> 5] = s;
    __syncthreads();
    s = 0.f;
    #pragma unroll
    for (int w = 0; w < 8; ++w) s += ssum[w];

    const float inv = 1.0f / s;
    e.x *= inv; e.y *= inv; e.z *= inv; e.w *= inv;

    bf16 h0, h1, h2, h3, l0, l1, l2, l3;
    split1(e.x, h0, l0); split1(e.y, h1, l1);
    split1(e.z, h2, l2); split1(e.w, h3, l3);
    *(uint2*)(g_ah + row * L + tid * 4) = make_uint2(pack_bf(h0, h1), pack_bf(h2, h3));
    *(uint2*)(g_al + row * L + tid * 4) = make_uint2(pack_bf(l0, l1), pack_bf(l2, l3));
}

// ---------------------------------------------------------------------------
// GEMM 3: att = alpha @ x2 (+ concat epilogue). grid (6, 8, 16)
// ---------------------------------------------------------------------------
__global__ __launch_bounds__(256, 2) void gemm_att(const float* __restrict__ x1,
                                                   float* __restrict__ out)
{
    extern __shared__ __align__(128) char gsm[];
    float acc[4][4][4] = {};

    const int b = blockIdx.z;
    const size_t m0 = (size_t)blockIdx.y * 128;
    const int n0 = blockIdx.x * 128;

    gemm_core(g_ah + ((size_t)b * L + m0) * L, g_al + ((size_t)b * L + m0) * L, L,
              g_x2Th + ((size_t)b * HDIM + n0) * L, g_x2Tl + ((size_t)b * HDIM + n0) * L, L,
              L, gsm, acc);

    const int tid = threadIdx.x, lane = tid & 31, wid = tid >> 5;
    const int wm = (wid & 1) * 64, wn = (wid >> 1) * 32;
    #pragma unroll
    for (int mi = 0; mi < 4; ++mi)
        #pragma unroll
        for (int ni = 0; ni < 4; ++ni)
            #pragma unroll
            for (int h = 0; h < 2; ++h) {
                const size_t m = m0 + wm + mi * 16 + (lane >> 2) + h * 8;
                const int n = n0 + wn + ni * 8 + (lane & 3) * 2;
                float2 A;
                A.x = acc[mi][ni][h * 2];
                A.y = acc[mi][ni][h * 2 + 1];
                const float* xp = x1 + ((size_t)b * L + m) * HDIM + n;
                float2 xv = *(const float2*)xp;
                float* op = out + ((size_t)b * L + m) * OUTW + n;
                *(float2*)(op)            = xv;
                *(float2*)(op + HDIM)     = A;
                *(float2*)(op + 2 * HDIM) = make_float2(xv.x * A.x, xv.y * A.y);
                *(float2*)(op + 3 * HDIM) = make_float2(xv.x - A.x, xv.y - A.y);
            }
}

// ---------------------------------------------------------------------------
extern "C" void kernel_launch(void* const* d_in, const int* in_sizes, int n_in,
                              void* d_out, int out_size)
{
    const float* x1 = (const float*)d_in[0];
    const float* x2 = (const float*)d_in[1];
    // d_in[2] = x1_mask (unused by reference)
    const int* x2_mask = (const int*)d_in[3];
    const float* W    = (const float*)d_in[4];
    const float* bias = (const float*)d_in[5];
    float* out = (float*)d_out;

    // opt-in to 80KB dynamic smem (idempotent; host-side, capture-safe)
    cudaFuncSetAttribute(gemm_proj,   cudaFuncAttributeMaxDynamicSharedMemorySize, SMEMB);
    cudaFuncSetAttribute(gemm_scores, cudaFuncAttributeMaxDynamicSharedMemorySize, SMEMB);
    cudaFuncSetAttribute(gemm_att,    cudaFuncAttributeMaxDynamicSharedMemorySize, SMEMB);

    const int n4x = BSZ * L * HDIM / 4;   // 3,145,728
    const int n4w = HDIM * HDIM / 4;      // 147,456

    split_kernel<<<n4x / 256, 256>>>(x1, 0, n4x);
    split_kernel<<<n4x / 256, 256>>>(x2, 1, n4x);
    split_kernel<<<n4w / 256, 256>>>(W, 2, n4w);
    transpose_split_kernel<<<dim3(HDIM / 32, L / 32, BSZ), 256>>>(x2);

    gemm_proj<<<dim3(HDIM / 128, (BSZ * L) / 128), 256, SMEMB>>>(bias, 0);
    gemm_proj<<<dim3(HDIM / 128, (BSZ * L) / 128), 256, SMEMB>>>(bias, 1);
    gemm_scores<<<dim3(L / 128, L / 128, BSZ), 256, SMEMB>>>(x2_mask);
    softmax_kernel<<<BSZ * L, 256>>>();
    gemm_att<<<dim3(HDIM / 128, L / 128, BSZ), 256, SMEMB>>>(x1, out);
}

// round 9
// speedup vs baseline: 2.5858x; 1.1852x over previous
#include <cuda_runtime.h>
#include <cuda_bf16.h>
#include <cuda_fp16.h>
#include <cstdint>

#define BSZ 16
#define L 1024
#define HDIM 768
#define OUTW (4*HDIM)

typedef __nv_bfloat16 bf16;

// ---------------- scratch (device globals; allocation-free rule) ------------
__device__ __align__(256) bf16 g_x1h[(size_t)BSZ*L*HDIM];
__device__ __align__(256) bf16 g_x1l[(size_t)BSZ*L*HDIM];
__device__ __align__(256) bf16 g_x2h[(size_t)BSZ*L*HDIM];
__device__ __align__(256) bf16 g_x2l[(size_t)BSZ*L*HDIM];
__device__ __align__(256) bf16 g_Wh [(size_t)HDIM*HDIM];
__device__ __align__(256) bf16 g_Wl [(size_t)HDIM*HDIM];
__device__ __align__(256) bf16 g_xph[(size_t)BSZ*L*HDIM];
__device__ __align__(256) bf16 g_xpl[(size_t)BSZ*L*HDIM];
__device__ __align__(256) bf16 g_yph[(size_t)BSZ*L*HDIM];
__device__ __align__(256) bf16 g_ypl[(size_t)BSZ*L*HDIM];
__device__ __align__(256) __half g_x2Th[(size_t)BSZ*HDIM*L];
__device__ __align__(256) __half g_ah [(size_t)BSZ*L*L];
__device__ float g_scores[(size_t)BSZ*L*L];

// ---------------- helpers ---------------------------------------------------
__device__ __forceinline__ uint32_t smem_u32(const void* p) {
    uint32_t a;
    asm("{ .reg .u64 t; cvta.to.shared.u64 t, %1; cvt.u32.u64 %0, t; }"
        : "=r"(a) : "l"(p));
    return a;
}
__device__ __forceinline__ void cp16(uint32_t dst, const void* src) {
    asm volatile("cp.async.cg.shared.global [%0], [%1], 16;"
                 :: "r"(dst), "l"(src) : "memory");
}
__device__ __forceinline__ void ldmx4(uint32_t (&r)[4], uint32_t addr) {
    asm volatile("ldmatrix.sync.aligned.m8n8.x4.shared.b16 {%0,%1,%2,%3}, [%4];"
                 : "=r"(r[0]), "=r"(r[1]), "=r"(r[2]), "=r"(r[3]) : "r"(addr));
}
__device__ __forceinline__ void mma16816(float (&c)[4], const uint32_t (&a)[4],
                                         uint32_t b0, uint32_t b1) {
    asm volatile(
        "mma.sync.aligned.m16n8k16.row.col.f32.bf16.bf16.f32 "
        "{%0,%1,%2,%3}, {%4,%5,%6,%7}, {%8,%9}, {%0,%1,%2,%3};"
        : "+f"(c[0]), "+f"(c[1]), "+f"(c[2]), "+f"(c[3])
        : "r"(a[0]), "r"(a[1]), "r"(a[2]), "r"(a[3]), "r"(b0), "r"(b1));
}
__device__ __forceinline__ void mma16816_f16(float (&c)[4], const uint32_t (&a)[4],
                                             uint32_t b0, uint32_t b1) {
    asm volatile(
        "mma.sync.aligned.m16n8k16.row.col.f32.f16.f16.f32 "
        "{%0,%1,%2,%3}, {%4,%5,%6,%7}, {%8,%9}, {%0,%1,%2,%3};"
        : "+f"(c[0]), "+f"(c[1]), "+f"(c[2]), "+f"(c[3])
        : "r"(a[0]), "r"(a[1]), "r"(a[2]), "r"(a[3]), "r"(b0), "r"(b1));
}
__device__ __forceinline__ uint32_t pack_bf(bf16 a, bf16 b) {
    uint16_t ua = *(uint16_t*)&a, ub = *(uint16_t*)&b;
    return (uint32_t)ua | ((uint32_t)ub << 16);
}
__device__ __forceinline__ uint32_t pack_h(__half a, __half b) {
    uint16_t ua = *(uint16_t*)&a, ub = *(uint16_t*)&b;
    return (uint32_t)ua | ((uint32_t)ub << 16);
}
__device__ __forceinline__ void split1(float f, bf16& h, bf16& l) {
    h = __float2bfloat16(f);
    l = __float2bfloat16(f - __bfloat162float(h));
}

// smem tile: 128 rows x 80B (64B data + 16B pad -> conflict-free ldmatrix)
#define ROWB 80
#define TILEB (128 * ROWB)          // 10240
#define STAGEB (4 * TILEB)          // Ah,Al,Bh,Bl per stage = 40960
#define SMEMB (2 * STAGEB)          // double buffer = 81920
#define STAGEB1 (2 * TILEB)         // 1-pass: A,B per stage
#define SMEMB1 (2 * STAGEB1)        // 40960 (static)

// ---------------------------------------------------------------------------
// Fused split-bf16 mainloop (3 contributions): acc += Ah.Bh^T + Ah.Bl^T + Al.Bh^T
// ---------------------------------------------------------------------------
__device__ __forceinline__ void gemm_core(
    const bf16* __restrict__ Ah, const bf16* __restrict__ Al, int lda,
    const bf16* __restrict__ Bh, const bf16* __restrict__ Bl, int ldb,
    int K, char* smem, float (&acc)[4][4][4])
{
    const int tid  = threadIdx.x;
    const int lane = tid & 31;
    const int wid  = tid >> 5;
    const int wm   = (wid & 1) * 64;
    const int wn   = (wid >> 1) * 32;
    const uint32_t sbase = smem_u32(smem);
    const int nk = K >> 5;

    const int ra = tid >> 2, ca = tid & 3;
    const int rb = ra + 64;

    for (int i = -1; i < nk; ++i) {
        if (i + 1 < nk) {
            const int kt = (i + 1) << 5;
            const uint32_t st = sbase + ((i + 1) & 1) * STAGEB;
            const uint32_t o0 = ra * ROWB + ca * 16;
            const uint32_t o1 = rb * ROWB + ca * 16;
            cp16(st + o0,             Ah + (size_t)ra * lda + kt + ca * 8);
            cp16(st + o1,             Ah + (size_t)rb * lda + kt + ca * 8);
            cp16(st + TILEB + o0,     Al + (size_t)ra * lda + kt + ca * 8);
            cp16(st + TILEB + o1,     Al + (size_t)rb * lda + kt + ca * 8);
            cp16(st + 2*TILEB + o0,   Bh + (size_t)ra * ldb + kt + ca * 8);
            cp16(st + 2*TILEB + o1,   Bh + (size_t)rb * ldb + kt + ca * 8);
            cp16(st + 3*TILEB + o0,   Bl + (size_t)ra * ldb + kt + ca * 8);
            cp16(st + 3*TILEB + o1,   Bl + (size_t)rb * ldb + kt + ca * 8);
            asm volatile("cp.async.commit_group;" ::: "memory");
        }
        if (i < 0) continue;
        if (i + 1 < nk)
            asm volatile("cp.async.wait_group 1;" ::: "memory");
        else
            asm volatile("cp.async.wait_group 0;" ::: "memory");
        __syncthreads();

        const uint32_t sAh = sbase + (i & 1) * STAGEB;
        const uint32_t sAl = sAh + TILEB;
        const uint32_t sBh = sAh + 2 * TILEB;
        const uint32_t sBl = sAh + 3 * TILEB;
        #pragma unroll
        for (int kh = 0; kh < 2; ++kh) {
            const uint32_t coff = (uint32_t)(kh * 2 + (lane >> 4)) * 16;
            const uint32_t brow = (uint32_t)(wn + (lane & 15)) * ROWB + coff;
            uint32_t bh0[4], bh1[4], bl0[4], bl1[4];
            ldmx4(bh0, sBh + brow);
            ldmx4(bh1, sBh + brow + 16u * ROWB);
            ldmx4(bl0, sBl + brow);
            ldmx4(bl1, sBl + brow + 16u * ROWB);
            #pragma unroll
            for (int mi = 0; mi < 4; ++mi) {
                const uint32_t arow = (uint32_t)(wm + mi * 16 + (lane & 15)) * ROWB + coff;
                uint32_t ah[4], al[4];
                ldmx4(ah, sAh + arow);
                ldmx4(al, sAl + arow);
                mma16816(acc[mi][0], ah, bh0[0], bh0[2]);
                mma16816(acc[mi][1], ah, bh0[1], bh0[3]);
                mma16816(acc[mi][2], ah, bh1[0], bh1[2]);
                mma16816(acc[mi][3], ah, bh1[1], bh1[3]);
                mma16816(acc[mi][0], ah, bl0[0], bl0[2]);
                mma16816(acc[mi][1], ah, bl0[1], bl0[3]);
                mma16816(acc[mi][2], ah, bl1[0], bl1[2]);
                mma16816(acc[mi][3], ah, bl1[1], bl1[3]);
                mma16816(acc[mi][0], al, bh0[0], bh0[2]);
                mma16816(acc[mi][1], al, bh0[1], bh0[3]);
                mma16816(acc[mi][2], al, bh1[0], bh1[2]);
                mma16816(acc[mi][3], al, bh1[1], bh1[3]);
            }
        }
        __syncthreads();
    }
}

// ---------------------------------------------------------------------------
// Plain fp16 single-pass mainloop: acc += A.B^T
// ---------------------------------------------------------------------------
__device__ __forceinline__ void gemm_core_1p(
    const __half* __restrict__ A, int lda,
    const __half* __restrict__ B, int ldb,
    int K, char* smem, float (&acc)[4][4][4])
{
    const int tid  = threadIdx.x;
    const int lane = tid & 31;
    const int wid  = tid >> 5;
    const int wm   = (wid & 1) * 64;
    const int wn   = (wid >> 1) * 32;
    const uint32_t sbase = smem_u32(smem);
    const int nk = K >> 5;

    const int ra = tid >> 2, ca = tid & 3;
    const int rb = ra + 64;

    for (int i = -1; i < nk; ++i) {
        if (i + 1 < nk) {
            const int kt = (i + 1) << 5;
            const uint32_t st = sbase + ((i + 1) & 1) * STAGEB1;
            const uint32_t o0 = ra * ROWB + ca * 16;
            const uint32_t o1 = rb * ROWB + ca * 16;
            cp16(st + o0,         A + (size_t)ra * lda + kt + ca * 8);
            cp16(st + o1,         A + (size_t)rb * lda + kt + ca * 8);
            cp16(st + TILEB + o0, B + (size_t)ra * ldb + kt + ca * 8);
            cp16(st + TILEB + o1, B + (size_t)rb * ldb + kt + ca * 8);
            asm volatile("cp.async.commit_group;" ::: "memory");
        }
        if (i < 0) continue;
        if (i + 1 < nk)
            asm volatile("cp.async.wait_group 1;" ::: "memory");
        else
            asm volatile("cp.async.wait_group 0;" ::: "memory");
        __syncthreads();

        const uint32_t sA = sbase + (i & 1) * STAGEB1;
        const uint32_t sB = sA + TILEB;
        #pragma unroll
        for (int kh = 0; kh < 2; ++kh) {
            const uint32_t coff = (uint32_t)(kh * 2 + (lane >> 4)) * 16;
            const uint32_t brow = (uint32_t)(wn + (lane & 15)) * ROWB + coff;
            uint32_t bb0[4], bb1[4];
            ldmx4(bb0, sB + brow);
            ldmx4(bb1, sB + brow + 16u * ROWB);
            #pragma unroll
            for (int mi = 0; mi < 4; ++mi) {
                uint32_t aa[4];
                ldmx4(aa, sA + (uint32_t)(wm + mi * 16 + (lane & 15)) * ROWB + coff);
                mma16816_f16(acc[mi][0], aa, bb0[0], bb0[2]);
                mma16816_f16(acc[mi][1], aa, bb0[1], bb0[3]);
                mma16816_f16(acc[mi][2], aa, bb1[0], bb1[2]);
                mma16816_f16(acc[mi][3], aa, bb1[1], bb1[3]);
            }
        }
        __syncthreads();
    }
}

// ---------------------------------------------------------------------------
// Split kernels
// ---------------------------------------------------------------------------
__global__ __launch_bounds__(256) void split_kernel(const float* __restrict__ in,
                                                    int which, int n4)
{
    bf16 *hi, *lo;
    if (which == 0)      { hi = g_x1h; lo = g_x1l; }
    else if (which == 1) { hi = g_x2h; lo = g_x2l; }
    else                 { hi = g_Wh;  lo = g_Wl;  }
    int i = blockIdx.x * 256 + threadIdx.x;
    if (i >= n4) return;
    float4 v = ((const float4*)in)[i];
    bf16 h0, h1, h2, h3, l0, l1, l2, l3;
    split1(v.x, h0, l0); split1(v.y, h1, l1);
    split1(v.z, h2, l2); split1(v.w, h3, l3);
    ((uint2*)hi)[i] = make_uint2(pack_bf(h0, h1), pack_bf(h2, h3));
    ((uint2*)lo)[i] = make_uint2(pack_bf(l0, l1), pack_bf(l2, l3));
}

__global__ __launch_bounds__(256) void transpose_kernel(const float* __restrict__ x2)
{
    __shared__ float t[32][33];
    const int b = blockIdx.z;
    const int h0 = blockIdx.x * 32, l0 = blockIdx.y * 32;
    const int tx = threadIdx.x & 31, ty = threadIdx.x >> 5;   // ty 0..7
    const float* src = x2 + ((size_t)b * L + l0) * HDIM + h0;
    #pragma unroll
    for (int j = 0; j < 4; ++j)
        t[ty + j * 8][tx] = src[(size_t)(ty + j * 8) * HDIM + tx];
    __syncthreads();
    #pragma unroll
    for (int j = 0; j < 4; ++j) {
        int r = ty + j * 8;                                   // h-local
        size_t o = ((size_t)b * HDIM + h0 + r) * L + l0 + tx;
        g_x2Th[o] = __float2half(t[tx][r]);
    }
}

// ---------------------------------------------------------------------------
// GEMM 1: proj = relu(X @ W^T + b) -> bf16 hi/lo.  grid (6, 128)
// ---------------------------------------------------------------------------
__global__ __launch_bounds__(256, 2) void gemm_proj(const float* __restrict__ bias, int which)
{
    extern __shared__ __align__(128) char gsm[];
    float acc[4][4][4] = {};

    const bf16* Ah = which ? g_x2h : g_x1h;
    const bf16* Al = which ? g_x2l : g_x1l;
    bf16* Oh = which ? g_yph : g_xph;
    bf16* Ol = which ? g_ypl : g_xpl;
    const size_t m0 = (size_t)blockIdx.y * 128;
    const int n0 = blockIdx.x * 128;

    gemm_core(Ah + m0 * HDIM, Al + m0 * HDIM, HDIM,
              g_Wh + (size_t)n0 * HDIM, g_Wl + (size_t)n0 * HDIM, HDIM,
              HDIM, gsm, acc);

    const int tid = threadIdx.x, lane = tid & 31, wid = tid >> 5;
    const int wm = (wid & 1) * 64, wn = (wid >> 1) * 32;
    #pragma unroll
    for (int mi = 0; mi < 4; ++mi)
        #pragma unroll
        for (int ni = 0; ni < 4; ++ni)
            #pragma unroll
            for (int h = 0; h < 2; ++h) {
                const size_t m = m0 + wm + mi * 16 + (lane >> 2) + h * 8;
                const int n = n0 + wn + ni * 8 + (lane & 3) * 2;
                float f0 = fmaxf(acc[mi][ni][h * 2]     + bias[n],     0.f);
                float f1 = fmaxf(acc[mi][ni][h * 2 + 1] + bias[n + 1], 0.f);
                bf16 h0, l0, h1, l1;
                split1(f0, h0, l0); split1(f1, h1, l1);
                *(uint32_t*)(Oh + m * HDIM + n) = pack_bf(h0, h1);
                *(uint32_t*)(Ol + m * HDIM + n) = pack_bf(l0, l1);
            }
}

// ---------------------------------------------------------------------------
// GEMM 2: scores = xproj . yproj^T, -inf mask -> fp32.  grid (8, 8, 16)
// ---------------------------------------------------------------------------
__global__ __launch_bounds__(256, 2) void gemm_scores(const int* __restrict__ x2_mask)
{
    extern __shared__ __align__(128) char gsm[];
    float acc[4][4][4] = {};

    const int b = blockIdx.z;
    const size_t m0 = (size_t)blockIdx.y * 128;
    const int n0 = blockIdx.x * 128;
    const size_t boff = (size_t)b * L * HDIM;

    gemm_core(g_xph + boff + m0 * HDIM, g_xpl + boff + m0 * HDIM, HDIM,
              g_yph + boff + (size_t)n0 * HDIM, g_ypl + boff + (size_t)n0 * HDIM, HDIM,
              HDIM, gsm, acc);

    const int tid = threadIdx.x, lane = tid & 31, wid = tid >> 5;
    const int wm = (wid & 1) * 64, wn = (wid >> 1) * 32;
    const float NEGINF = __int_as_float(0xff800000u);
    const int* mrow = x2_mask + (size_t)b * L + n0;
    #pragma unroll
    for (int mi = 0; mi < 4; ++mi)
        #pragma unroll
        for (int ni = 0; ni < 4; ++ni)
            #pragma unroll
            for (int h = 0; h < 2; ++h) {
                const size_t m = m0 + wm + mi * 16 + (lane >> 2) + h * 8;
                const int n = wn + ni * 8 + (lane & 3) * 2;
                float2 o;
                o.x = mrow[n]     ? NEGINF : acc[mi][ni][h * 2];
                o.y = mrow[n + 1] ? NEGINF : acc[mi][ni][h * 2 + 1];
                *(float2*)(g_scores + ((size_t)b * L + m) * L + n0 + n) = o;
            }
}

// ---------------------------------------------------------------------------
// Softmax: fp32 scores in, fp16 alpha out. grid(16384), 256 threads.
// ---------------------------------------------------------------------------
__global__ __launch_bounds__(256) void softmax_kernel()
{
    const int tid = threadIdx.x;
    const size_t row = blockIdx.x;
    const float4* p = ((const float4*)g_scores) + row * (L / 4) + tid;
    float4 v = *p;

    __shared__ float smax[8];
    __shared__ float ssum[8];

    float m = fmaxf(fmaxf(v.x, v.y), fmaxf(v.z, v.w));
    #pragma unroll
    for (int o = 16; o > 0; o >>= 1)
        m = fmaxf(m, __shfl_xor_sync(0xffffffffu, m, o));
    if ((tid & 31) == 0) smax[tid >> 5] = m;
    __syncthreads();
    m = smax[0];
    #pragma unroll
    for (int w = 1; w < 8; ++w) m = fmaxf(m, smax[w]);

    float4 e;
    e.x = expf(v.x - m); e.y = expf(v.y - m);
    e.z = expf(v.z - m); e.w = expf(v.w - m);
    float s = (e.x + e.y) + (e.z + e.w);
    #pragma unroll
    for (int o = 16; o > 0; o >>= 1)
        s += __shfl_xor_sync(0xffffffffu, s, o);
    if ((tid & 31) == 0) ssum[tid >> 5] = s;
    __syncthreads();
    s = 0.f;
    #pragma unroll
    for (int w = 0; w < 8; ++w) s += ssum[w];

    const float inv = 1.0f / s;
    e.x *= inv; e.y *= inv; e.z *= inv; e.w *= inv;

    *(uint2*)(g_ah + row * L + tid * 4) = make_uint2(
        pack_h(__float2half(e.x), __float2half(e.y)),
        pack_h(__float2half(e.z), __float2half(e.w)));
}

// ---------------------------------------------------------------------------
// GEMM 3: att = alpha @ x2 (single-pass fp16) + concat epilogue. grid (6, 8, 16)
// ---------------------------------------------------------------------------
__global__ __launch_bounds__(256, 2) void gemm_att(const float* __restrict__ x1,
                                                   float* __restrict__ out)
{
    __shared__ __align__(128) char gsm[SMEMB1];
    float acc[4][4][4] = {};

    const int b = blockIdx.z;
    const size_t m0 = (size_t)blockIdx.y * 128;
    const int n0 = blockIdx.x * 128;

    gemm_core_1p(g_ah + ((size_t)b * L + m0) * L, L,
                 g_x2Th + ((size_t)b * HDIM + n0) * L, L,
                 L, gsm, acc);

    const int tid = threadIdx.x, lane = tid & 31, wid = tid >> 5;
    const int wm = (wid & 1) * 64, wn = (wid >> 1) * 32;
    #pragma unroll
    for (int mi = 0; mi < 4; ++mi)
        #pragma unroll
        for (int ni = 0; ni < 4; ++ni)
            #pragma unroll
            for (int h = 0; h < 2; ++h) {
                const size_t m = m0 + wm + mi * 16 + (lane >> 2) + h * 8;
                const int n = n0 + wn + ni * 8 + (lane & 3) * 2;
                float2 A;
                A.x = acc[mi][ni][h * 2];
                A.y = acc[mi][ni][h * 2 + 1];
                const float* xp = x1 + ((size_t)b * L + m) * HDIM + n;
                float2 xv = *(const float2*)xp;
                float* op = out + ((size_t)b * L + m) * OUTW + n;
                *(float2*)(op)            = xv;
                *(float2*)(op + HDIM)     = A;
                *(float2*)(op + 2 * HDIM) = make_float2(xv.x * A.x, xv.y * A.y);
                *(float2*)(op + 3 * HDIM) = make_float2(xv.x - A.x, xv.y - A.y);
            }
}

// ---------------------------------------------------------------------------
extern "C" void kernel_launch(void* const* d_in, const int* in_sizes, int n_in,
                              void* d_out, int out_size)
{
    const float* x1 = (const float*)d_in[0];
    const float* x2 = (const float*)d_in[1];
    // d_in[2] = x1_mask (unused by reference)
    const int* x2_mask = (const int*)d_in[3];
    const float* W    = (const float*)d_in[4];
    const float* bias = (const float*)d_in[5];
    float* out = (float*)d_out;

    // opt-in to 80KB dynamic smem (idempotent; host-side, capture-safe)
    cudaFuncSetAttribute(gemm_proj,   cudaFuncAttributeMaxDynamicSharedMemorySize, SMEMB);
    cudaFuncSetAttribute(gemm_scores, cudaFuncAttributeMaxDynamicSharedMemorySize, SMEMB);

    const int n4x = BSZ * L * HDIM / 4;   // 3,145,728
    const int n4w = HDIM * HDIM / 4;      // 147,456

    split_kernel<<<n4x / 256, 256>>>(x1, 0, n4x);
    split_kernel<<<n4x / 256, 256>>>(x2, 1, n4x);
    split_kernel<<<n4w / 256, 256>>>(W, 2, n4w);
    transpose_kernel<<<dim3(HDIM / 32, L / 32, BSZ), 256>>>(x2);

    gemm_proj<<<dim3(HDIM / 128, (BSZ * L) / 128), 256, SMEMB>>>(bias, 0);
    gemm_proj<<<dim3(HDIM / 128, (BSZ * L) / 128), 256, SMEMB>>>(bias, 1);
    gemm_scores<<<dim3(L / 128, L / 128, BSZ), 256, SMEMB>>>(x2_mask);
    softmax_kernel<<<BSZ * L, 256>>>();
    gemm_att<<<dim3(HDIM / 128, L / 128, BSZ), 256>>>(x1, out);
}

// round 11
// speedup vs baseline: 3.6434x; 1.4090x over previous
#include <cuda_runtime.h>
#include <cuda_bf16.h>
#include <cuda_fp16.h>
#include <cstdint>

#define BSZ 16
#define L 1024
#define HDIM 768
#define OUTW (4*HDIM)

typedef __nv_bfloat16 bf16;

// ---------------- scratch (device globals; allocation-free rule) ------------
__device__ __align__(256) bf16 g_x1h[(size_t)BSZ*L*HDIM];
__device__ __align__(256) bf16 g_x1l[(size_t)BSZ*L*HDIM];
__device__ __align__(256) bf16 g_x2h[(size_t)BSZ*L*HDIM];   // gathered (compacted) x2 rows hi
__device__ __align__(256) bf16 g_x2l[(size_t)BSZ*L*HDIM];   // gathered (compacted) x2 rows lo
__device__ __align__(256) bf16 g_Wh [(size_t)HDIM*HDIM];
__device__ __align__(256) bf16 g_Wl [(size_t)HDIM*HDIM];
__device__ __align__(256) bf16 g_xph[(size_t)BSZ*L*HDIM];
__device__ __align__(256) bf16 g_xpl[(size_t)BSZ*L*HDIM];
__device__ __align__(256) bf16 g_yph[(size_t)BSZ*L*HDIM];   // compacted y-proj hi
__device__ __align__(256) bf16 g_ypl[(size_t)BSZ*L*HDIM];   // compacted y-proj lo
__device__ __align__(256) __half g_x2Th[(size_t)BSZ*HDIM*L]; // gathered transpose (compacted cols)
__device__ __align__(256) __half g_ah [(size_t)BSZ*L*L];     // alpha (compacted cols)
__device__ float g_scores[(size_t)BSZ*L*L];
__device__ int g_cnt[BSZ];
__device__ int g_idx[BSZ][L];

// ---------------- helpers ---------------------------------------------------
__device__ __forceinline__ uint32_t smem_u32(const void* p) {
    uint32_t a;
    asm("{ .reg .u64 t; cvta.to.shared.u64 t, %1; cvt.u32.u64 %0, t; }"
        : "=r"(a) : "l"(p));
    return a;
}
__device__ __forceinline__ void cp16(uint32_t dst, const void* src) {
    asm volatile("cp.async.cg.shared.global [%0], [%1], 16;"
                 :: "r"(dst), "l"(src) : "memory");
}
__device__ __forceinline__ void ldmx4(uint32_t (&r)[4], uint32_t addr) {
    asm volatile("ldmatrix.sync.aligned.m8n8.x4.shared.b16 {%0,%1,%2,%3}, [%4];"
                 : "=r"(r[0]), "=r"(r[1]), "=r"(r[2]), "=r"(r[3]) : "r"(addr));
}
__device__ __forceinline__ void mma16816(float (&c)[4], const uint32_t (&a)[4],
                                         uint32_t b0, uint32_t b1) {
    asm volatile(
        "mma.sync.aligned.m16n8k16.row.col.f32.bf16.bf16.f32 "
        "{%0,%1,%2,%3}, {%4,%5,%6,%7}, {%8,%9}, {%0,%1,%2,%3};"
        : "+f"(c[0]), "+f"(c[1]), "+f"(c[2]), "+f"(c[3])
        : "r"(a[0]), "r"(a[1]), "r"(a[2]), "r"(a[3]), "r"(b0), "r"(b1));
}
__device__ __forceinline__ void mma16816_f16(float (&c)[4], const uint32_t (&a)[4],
                                             uint32_t b0, uint32_t b1) {
    asm volatile(
        "mma.sync.aligned.m16n8k16.row.col.f32.f16.f16.f32 "
        "{%0,%1,%2,%3}, {%4,%5,%6,%7}, {%8,%9}, {%0,%1,%2,%3};"
        : "+f"(c[0]), "+f"(c[1]), "+f"(c[2]), "+f"(c[3])
        : "r"(a[0]), "r"(a[1]), "r"(a[2]), "r"(a[3]), "r"(b0), "r"(b1));
}
__device__ __forceinline__ uint32_t pack_bf(bf16 a, bf16 b) {
    uint16_t ua = *(uint16_t*)&a, ub = *(uint16_t*)&b;
    return (uint32_t)ua | ((uint32_t)ub << 16);
}
__device__ __forceinline__ uint32_t pack_h(__half a, __half b) {
    uint16_t ua = *(uint16_t*)&a, ub = *(uint16_t*)&b;
    return (uint32_t)ua | ((uint32_t)ub << 16);
}
__device__ __forceinline__ void split1(float f, bf16& h, bf16& l) {
    h = __float2bfloat16(f);
    l = __float2bfloat16(f - __bfloat162float(h));
}

#define ROWB 80
#define TILEB (128 * ROWB)
#define STAGEB (4 * TILEB)
#define SMEMB (2 * STAGEB)
#define STAGEB1 (2 * TILEB)
#define SMEMB1 (2 * STAGEB1)

// ---------------------------------------------------------------------------
// Fused split-bf16 mainloop (3 contributions)
// ---------------------------------------------------------------------------
__device__ __forceinline__ void gemm_core(
    const bf16* __restrict__ Ah, const bf16* __restrict__ Al, int lda,
    const bf16* __restrict__ Bh, const bf16* __restrict__ Bl, int ldb,
    int K, char* smem, float (&acc)[4][4][4])
{
    const int tid  = threadIdx.x;
    const int lane = tid & 31;
    const int wid  = tid >> 5;
    const int wm   = (wid & 1) * 64;
    const int wn   = (wid >> 1) * 32;
    const uint32_t sbase = smem_u32(smem);
    const int nk = K >> 5;

    const int ra = tid >> 2, ca = tid & 3;
    const int rb = ra + 64;

    for (int i = -1; i < nk; ++i) {
        if (i + 1 < nk) {
            const int kt = (i + 1) << 5;
            const uint32_t st = sbase + ((i + 1) & 1) * STAGEB;
            const uint32_t o0 = ra * ROWB + ca * 16;
            const uint32_t o1 = rb * ROWB + ca * 16;
            cp16(st + o0,             Ah + (size_t)ra * lda + kt + ca * 8);
            cp16(st + o1,             Ah + (size_t)rb * lda + kt + ca * 8);
            cp16(st + TILEB + o0,     Al + (size_t)ra * lda + kt + ca * 8);
            cp16(st + TILEB + o1,     Al + (size_t)rb * lda + kt + ca * 8);
            cp16(st + 2*TILEB + o0,   Bh + (size_t)ra * ldb + kt + ca * 8);
            cp16(st + 2*TILEB + o1,   Bh + (size_t)rb * ldb + kt + ca * 8);
            cp16(st + 3*TILEB + o0,   Bl + (size_t)ra * ldb + kt + ca * 8);
            cp16(st + 3*TILEB + o1,   Bl + (size_t)rb * ldb + kt + ca * 8);
            asm volatile("cp.async.commit_group;" ::: "memory");
        }
        if (i < 0) continue;
        if (i + 1 < nk)
            asm volatile("cp.async.wait_group 1;" ::: "memory");
        else
            asm volatile("cp.async.wait_group 0;" ::: "memory");
        __syncthreads();

        const uint32_t sAh = sbase + (i & 1) * STAGEB;
        const uint32_t sAl = sAh + TILEB;
        const uint32_t sBh = sAh + 2 * TILEB;
        const uint32_t sBl = sAh + 3 * TILEB;
        #pragma unroll
        for (int kh = 0; kh < 2; ++kh) {
            const uint32_t coff = (uint32_t)(kh * 2 + (lane >> 4)) * 16;
            const uint32_t brow = (uint32_t)(wn + (lane & 15)) * ROWB + coff;
            uint32_t bh0[4], bh1[4], bl0[4], bl1[4];
            ldmx4(bh0, sBh + brow);
            ldmx4(bh1, sBh + brow + 16u * ROWB);
            ldmx4(bl0, sBl + brow);
            ldmx4(bl1, sBl + brow + 16u * ROWB);
            #pragma unroll
            for (int mi = 0; mi < 4; ++mi) {
                const uint32_t arow = (uint32_t)(wm + mi * 16 + (lane & 15)) * ROWB + coff;
                uint32_t ah[4], al[4];
                ldmx4(ah, sAh + arow);
                ldmx4(al, sAl + arow);
                mma16816(acc[mi][0], ah, bh0[0], bh0[2]);
                mma16816(acc[mi][1], ah, bh0[1], bh0[3]);
                mma16816(acc[mi][2], ah, bh1[0], bh1[2]);
                mma16816(acc[mi][3], ah, bh1[1], bh1[3]);
                mma16816(acc[mi][0], ah, bl0[0], bl0[2]);
                mma16816(acc[mi][1], ah, bl0[1], bl0[3]);
                mma16816(acc[mi][2], ah, bl1[0], bl1[2]);
                mma16816(acc[mi][3], ah, bl1[1], bl1[3]);
                mma16816(acc[mi][0], al, bh0[0], bh0[2]);
                mma16816(acc[mi][1], al, bh0[1], bh0[3]);
                mma16816(acc[mi][2], al, bh1[0], bh1[2]);
                mma16816(acc[mi][3], al, bh1[1], bh1[3]);
            }
        }
        __syncthreads();
    }
}

// ---------------------------------------------------------------------------
// Plain fp16 single-pass mainloop
// ---------------------------------------------------------------------------
__device__ __forceinline__ void gemm_core_1p(
    const __half* __restrict__ A, int lda,
    const __half* __restrict__ B, int ldb,
    int K, char* smem, float (&acc)[4][4][4])
{
    const int tid  = threadIdx.x;
    const int lane = tid & 31;
    const int wid  = tid >> 5;
    const int wm   = (wid & 1) * 64;
    const int wn   = (wid >> 1) * 32;
    const uint32_t sbase = smem_u32(smem);
    const int nk = K >> 5;

    const int ra = tid >> 2, ca = tid & 3;
    const int rb = ra + 64;

    for (int i = -1; i < nk; ++i) {
        if (i + 1 < nk) {
            const int kt = (i + 1) << 5;
            const uint32_t st = sbase + ((i + 1) & 1) * STAGEB1;
            const uint32_t o0 = ra * ROWB + ca * 16;
            const uint32_t o1 = rb * ROWB + ca * 16;
            cp16(st + o0,         A + (size_t)ra * lda + kt + ca * 8);
            cp16(st + o1,         A + (size_t)rb * lda + kt + ca * 8);
            cp16(st + TILEB + o0, B + (size_t)ra * ldb + kt + ca * 8);
            cp16(st + TILEB + o1, B + (size_t)rb * ldb + kt + ca * 8);
            asm volatile("cp.async.commit_group;" ::: "memory");
        }
        if (i < 0) continue;
        if (i + 1 < nk)
            asm volatile("cp.async.wait_group 1;" ::: "memory");
        else
            asm volatile("cp.async.wait_group 0;" ::: "memory");
        __syncthreads();

        const uint32_t sA = sbase + (i & 1) * STAGEB1;
        const uint32_t sB = sA + TILEB;
        #pragma unroll
        for (int kh = 0; kh < 2; ++kh) {
            const uint32_t coff = (uint32_t)(kh * 2 + (lane >> 4)) * 16;
            const uint32_t brow = (uint32_t)(wn + (lane & 15)) * ROWB + coff;
            uint32_t bb0[4], bb1[4];
            ldmx4(bb0, sB + brow);
            ldmx4(bb1, sB + brow + 16u * ROWB);
            #pragma unroll
            for (int mi = 0; mi < 4; ++mi) {
                uint32_t aa[4];
                ldmx4(aa, sA + (uint32_t)(wm + mi * 16 + (lane & 15)) * ROWB + coff);
                mma16816_f16(acc[mi][0], aa, bb0[0], bb0[2]);
                mma16816_f16(acc[mi][1], aa, bb0[1], bb0[3]);
                mma16816_f16(acc[mi][2], aa, bb1[0], bb1[2]);
                mma16816_f16(acc[mi][3], aa, bb1[1], bb1[3]);
            }
        }
        __syncthreads();
    }
}

// ---------------------------------------------------------------------------
// Index build: per-batch compacted list of unmasked columns (block scan)
// ---------------------------------------------------------------------------
__global__ __launch_bounds__(256) void index_kernel(const int* __restrict__ x2_mask)
{
    const int b = blockIdx.x, tid = threadIdx.x;
    __shared__ int wsum[8];
    const int* m = x2_mask + (size_t)b * L;
    const int base = tid * 4;
    int keep[4], cnt = 0;
    #pragma unroll
    for (int j = 0; j < 4; ++j) { keep[j] = (m[base + j] == 0); cnt += keep[j]; }
    const int lane = tid & 31, w = tid >> 5;
    int v = cnt;
    #pragma unroll
    for (int o = 1; o < 32; o <<= 1) {
        int t = __shfl_up_sync(0xffffffffu, v, o);
        if (lane >= o) v += t;
    }
    if (lane == 31) wsum[w] = v;
    __syncthreads();
    int woff = 0;
    for (int i = 0; i < w; ++i) woff += wsum[i];
    int pos = woff + v - cnt;   // exclusive prefix
    #pragma unroll
    for (int j = 0; j < 4; ++j)
        if (keep[j]) g_idx[b][pos++] = base + j;
    if (tid == 255) g_cnt[b] = woff + v;
}

// ---------------------------------------------------------------------------
// Split kernels (x1, W)
// ---------------------------------------------------------------------------
__global__ __launch_bounds__(256) void split_kernel(const float* __restrict__ in,
                                                    int which, int n4)
{
    bf16 *hi, *lo;
    if (which == 0) { hi = g_x1h; lo = g_x1l; }
    else            { hi = g_Wh;  lo = g_Wl;  }
    int i = blockIdx.x * 256 + threadIdx.x;
    if (i >= n4) return;
    float4 v = ((const float4*)in)[i];
    bf16 h0, h1, h2, h3, l0, l1, l2, l3;
    split1(v.x, h0, l0); split1(v.y, h1, l1);
    split1(v.z, h2, l2); split1(v.w, h3, l3);
    ((uint2*)hi)[i] = make_uint2(pack_bf(h0, h1), pack_bf(h2, h3));
    ((uint2*)lo)[i] = make_uint2(pack_bf(l0, l1), pack_bf(l2, l3));
}

// ---------------------------------------------------------------------------
// Gather + split x2 rows (compacted). grid (L, BSZ), 192 threads.
// ---------------------------------------------------------------------------
__global__ __launch_bounds__(192) void gather_split_x2(const float* __restrict__ x2)
{
    const int b = blockIdx.y, r = blockIdx.x, t = threadIdx.x;
    const int c = g_cnt[b];
    const int cpad = (c + 127) & ~127;
    if (r >= cpad) return;
    const size_t dsto = ((size_t)b * L + r) * HDIM + t * 4;
    if (r < c) {
        const int j = g_idx[b][r];
        float4 v = *(const float4*)(x2 + ((size_t)b * L + j) * HDIM + t * 4);
        bf16 h0, h1, h2, h3, l0, l1, l2, l3;
        split1(v.x, h0, l0); split1(v.y, h1, l1);
        split1(v.z, h2, l2); split1(v.w, h3, l3);
        *(uint2*)(g_x2h + dsto) = make_uint2(pack_bf(h0, h1), pack_bf(h2, h3));
        *(uint2*)(g_x2l + dsto) = make_uint2(pack_bf(l0, l1), pack_bf(l2, l3));
    } else {
        *(uint2*)(g_x2h + dsto) = make_uint2(0u, 0u);
        *(uint2*)(g_x2l + dsto) = make_uint2(0u, 0u);
    }
}

// ---------------------------------------------------------------------------
// Gathered transpose: x2T[b][h][k] = x2[b][idx[k]][h] (fp16), zero pad.
// grid (HDIM/32, L/32, BSZ)
// ---------------------------------------------------------------------------
__global__ __launch_bounds__(256) void transpose_gather_kernel(const float* __restrict__ x2)
{
    __shared__ float t[32][33];
    const int b = blockIdx.z;
    const int c = g_cnt[b];
    const int cpad = (c + 127) & ~127;
    const int h0 = blockIdx.x * 32, l0 = blockIdx.y * 32;
    if (l0 >= cpad) return;
    const int tx = threadIdx.x & 31, ty = threadIdx.x >> 5;
    #pragma unroll
    for (int j = 0; j < 4; ++j) {
        const int li = ty + j * 8;
        const int lg = l0 + li;
        float v = 0.f;
        if (lg < c) {
            const int src = g_idx[b][lg];
            v = x2[((size_t)b * L + src) * HDIM + h0 + tx];
        }
        t[li][tx] = v;
    }
    __syncthreads();
    #pragma unroll
    for (int j = 0; j < 4; ++j) {
        const int r = ty + j * 8;   // h-local
        g_x2Th[((size_t)b * HDIM + h0 + r) * L + l0 + tx] = __float2half(t[tx][r]);
    }
}

// ---------------------------------------------------------------------------
// GEMM 1a: xproj = relu(x1 @ W^T + b).  grid (6, 128)
// ---------------------------------------------------------------------------
__global__ __launch_bounds__(256, 2) void gemm_proj_x(const float* __restrict__ bias)
{
    extern __shared__ __align__(128) char gsm[];
    float acc[4][4][4] = {};

    const size_t m0 = (size_t)blockIdx.y * 128;
    const int n0 = blockIdx.x * 128;

    gemm_core(g_x1h + m0 * HDIM, g_x1l + m0 * HDIM, HDIM,
              g_Wh + (size_t)n0 * HDIM, g_Wl + (size_t)n0 * HDIM, HDIM,
              HDIM, gsm, acc);

    const int tid = threadIdx.x, lane = tid & 31, wid = tid >> 5;
    const int wm = (wid & 1) * 64, wn = (wid >> 1) * 32;
    #pragma unroll
    for (int mi = 0; mi < 4; ++mi)
        #pragma unroll
        for (int ni = 0; ni < 4; ++ni)
            #pragma unroll
            for (int h = 0; h < 2; ++h) {
                const size_t m = m0 + wm + mi * 16 + (lane >> 2) + h * 8;
                const int n = n0 + wn + ni * 8 + (lane & 3) * 2;
                float f0 = fmaxf(acc[mi][ni][h * 2]     + bias[n],     0.f);
                float f1 = fmaxf(acc[mi][ni][h * 2 + 1] + bias[n + 1], 0.f);
                bf16 h0, l0, h1, l1;
                split1(f0, h0, l0); split1(f1, h1, l1);
                *(uint32_t*)(g_xph + m * HDIM + n) = pack_bf(h0, h1);
                *(uint32_t*)(g_xpl + m * HDIM + n) = pack_bf(l0, l1);
            }
}

// ---------------------------------------------------------------------------
// GEMM 1b: yproj over compacted x2 rows.  grid (6, 8, 16) early-exit.
// ---------------------------------------------------------------------------
__global__ __launch_bounds__(256, 2) void gemm_proj_y(const float* __restrict__ bias)
{
    extern __shared__ __align__(128) char gsm[];
    const int b = blockIdx.z;
    const int cpad = (g_cnt[b] + 127) & ~127;
    const size_t m0 = (size_t)blockIdx.y * 128;
    if ((int)m0 >= cpad) return;

    float acc[4][4][4] = {};
    const int n0 = blockIdx.x * 128;
    const size_t boff = (size_t)b * L * HDIM;

    gemm_core(g_x2h + boff + m0 * HDIM, g_x2l + boff + m0 * HDIM, HDIM,
              g_Wh + (size_t)n0 * HDIM, g_Wl + (size_t)n0 * HDIM, HDIM,
              HDIM, gsm, acc);

    const int tid = threadIdx.x, lane = tid & 31, wid = tid >> 5;
    const int wm = (wid & 1) * 64, wn = (wid >> 1) * 32;
    #pragma unroll
    for (int mi = 0; mi < 4; ++mi)
        #pragma unroll
        for (int ni = 0; ni < 4; ++ni)
            #pragma unroll
            for (int h = 0; h < 2; ++h) {
                const size_t m = m0 + wm + mi * 16 + (lane >> 2) + h * 8;
                const int n = n0 + wn + ni * 8 + (lane & 3) * 2;
                float f0 = fmaxf(acc[mi][ni][h * 2]     + bias[n],     0.f);
                float f1 = fmaxf(acc[mi][ni][h * 2 + 1] + bias[n + 1], 0.f);
                bf16 h0, l0, h1, l1;
                split1(f0, h0, l0); split1(f1, h1, l1);
                *(uint32_t*)(g_yph + boff + m * HDIM + n) = pack_bf(h0, h1);
                *(uint32_t*)(g_ypl + boff + m * HDIM + n) = pack_bf(l0, l1);
            }
}

// ---------------------------------------------------------------------------
// GEMM 2: scores over compacted cols, -inf beyond count. grid (8, 8, 16)
// ---------------------------------------------------------------------------
__global__ __launch_bounds__(256, 2) void gemm_scores()
{
    extern __shared__ __align__(128) char gsm[];
    const int b = blockIdx.z;
    const int c = g_cnt[b];
    const int cpad = (c + 127) & ~127;
    const int n0 = blockIdx.x * 128;
    if (n0 >= cpad) return;

    float acc[4][4][4] = {};
    const size_t m0 = (size_t)blockIdx.y * 128;
    const size_t boff = (size_t)b * L * HDIM;

    gemm_core(g_xph + boff + m0 * HDIM, g_xpl + boff + m0 * HDIM, HDIM,
              g_yph + boff + (size_t)n0 * HDIM, g_ypl + boff + (size_t)n0 * HDIM, HDIM,
              HDIM, gsm, acc);

    const int tid = threadIdx.x, lane = tid & 31, wid = tid >> 5;
    const int wm = (wid & 1) * 64, wn = (wid >> 1) * 32;
    const float NEGINF = __int_as_float(0xff800000u);
    #pragma unroll
    for (int mi = 0; mi < 4; ++mi)
        #pragma unroll
        for (int ni = 0; ni < 4; ++ni)
            #pragma unroll
            for (int h = 0; h < 2; ++h) {
                const size_t m = m0 + wm + mi * 16 + (lane >> 2) + h * 8;
                const int n = n0 + wn + ni * 8 + (lane & 3) * 2;
                float2 o;
                o.x = (n     >= c) ? NEGINF : acc[mi][ni][h * 2];
                o.y = (n + 1 >= c) ? NEGINF : acc[mi][ni][h * 2 + 1];
                *(float2*)(g_scores + ((size_t)b * L + m) * L + n) = o;
            }
}

// ---------------------------------------------------------------------------
// Softmax over compacted cols; fp16 alpha out. grid(16384), 256 threads.
// ---------------------------------------------------------------------------
__global__ __launch_bounds__(256) void softmax_kernel()
{
    const int tid = threadIdx.x;
    const size_t row = blockIdx.x;
    const int b = (int)(row >> 10);
    const int cpad = (g_cnt[b] + 127) & ~127;
    const int col = tid * 4;
    const float NEGINF = __int_as_float(0xff800000u);

    float4 v = make_float4(NEGINF, NEGINF, NEGINF, NEGINF);
    if (col < cpad)
        v = *(((const float4*)g_scores) + row * (L / 4) + tid);

    __shared__ float smax[8];
    __shared__ float ssum[8];

    float m = fmaxf(fmaxf(v.x, v.y), fmaxf(v.z, v.w));
    #pragma unroll
    for (int o = 16; o > 0; o >>= 1)
        m = fmaxf(m, __shfl_xor_sync(0xffffffffu, m, o));
    if ((tid & 31) == 0) smax[tid >> 5] = m;
    __syncthreads();
    m = smax[0];
    #pragma unroll
    for (int w = 1; w < 8; ++w) m = fmaxf(m, smax[w]);

    float4 e;
    e.x = expf(v.x - m); e.y = expf(v.y - m);
    e.z = expf(v.z - m); e.w = expf(v.w - m);
    float s = (e.x + e.y) + (e.z + e.w);
    #pragma unroll
    for (int o = 16; o > 0; o >>= 1)
        s += __shfl_xor_sync(0xffffffffu, s, o);
    if ((tid & 31) == 0) ssum[tid >> 5] = s;
    __syncthreads();
    s = 0.f;
    #pragma unroll
    for (int w = 0; w < 8; ++w) s += ssum[w];

    const float inv = 1.0f / s;
    if (col < cpad) {
        e.x *= inv; e.y *= inv; e.z *= inv; e.w *= inv;
        *(uint2*)(g_ah + row * L + col) = make_uint2(
            pack_h(__float2half(e.x), __float2half(e.y)),
            pack_h(__float2half(e.z), __float2half(e.w)));
    }
}

// ---------------------------------------------------------------------------
// GEMM 3: att = alpha @ x2 over compacted K + concat epilogue. grid (6, 8, 16)
// ---------------------------------------------------------------------------
__global__ __launch_bounds__(256, 2) void gemm_att(const float* __restrict__ x1,
                                                   float* __restrict__ out)
{
    __shared__ __align__(128) char gsm[SMEMB1];
    float acc[4][4][4] = {};

    const int b = blockIdx.z;
    const int cpad = (g_cnt[b] + 127) & ~127;
    const size_t m0 = (size_t)blockIdx.y * 128;
    const int n0 = blockIdx.x * 128;

    gemm_core_1p(g_ah + ((size_t)b * L + m0) * L, L,
                 g_x2Th + ((size_t)b * HDIM + n0) * L, L,
                 cpad, gsm, acc);

    const int tid = threadIdx.x, lane = tid & 31, wid = tid >> 5;
    const int wm = (wid & 1) * 64, wn = (wid >> 1) * 32;
    #pragma unroll
    for (int mi = 0; mi < 4; ++mi)
        #pragma unroll
        for (int ni = 0; ni < 4; ++ni)
            #pragma unroll
            for (int h = 0; h < 2; ++h) {
                const size_t m = m0 + wm + mi * 16 + (lane >> 2) + h * 8;
                const int n = n0 + wn + ni * 8 + (lane & 3) * 2;
                float2 A;
                A.x = acc[mi][ni][h * 2];
                A.y = acc[mi][ni][h * 2 + 1];
                const float* xp = x1 + ((size_t)b * L + m) * HDIM + n;
                float2 xv = *(const float2*)xp;
                float* op = out + ((size_t)b * L + m) * OUTW + n;
                *(float2*)(op)            = xv;
                *(float2*)(op + HDIM)     = A;
                *(float2*)(op + 2 * HDIM) = make_float2(xv.x * A.x, xv.y * A.y);
                *(float2*)(op + 3 * HDIM) = make_float2(xv.x - A.x, xv.y - A.y);
            }
}

// ---------------------------------------------------------------------------
extern "C" void kernel_launch(void* const* d_in, const int* in_sizes, int n_in,
                              void* d_out, int out_size)
{
    const float* x1 = (const float*)d_in[0];
    const float* x2 = (const float*)d_in[1];
    // d_in[2] = x1_mask (unused by reference)
    const int* x2_mask = (const int*)d_in[3];
    const float* W    = (const float*)d_in[4];
    const float* bias = (const float*)d_in[5];
    float* out = (float*)d_out;

    cudaFuncSetAttribute(gemm_proj_x, cudaFuncAttributeMaxDynamicSharedMemorySize, SMEMB);
    cudaFuncSetAttribute(gemm_proj_y, cudaFuncAttributeMaxDynamicSharedMemorySize, SMEMB);
    cudaFuncSetAttribute(gemm_scores, cudaFuncAttributeMaxDynamicSharedMemorySize, SMEMB);

    const int n4x = BSZ * L * HDIM / 4;
    const int n4w = HDIM * HDIM / 4;

    index_kernel<<<BSZ, 256>>>(x2_mask);
    split_kernel<<<n4x / 256, 256>>>(x1, 0, n4x);
    split_kernel<<<n4w / 256, 256>>>(W, 1, n4w);
    gather_split_x2<<<dim3(L, BSZ), 192>>>(x2);
    transpose_gather_kernel<<<dim3(HDIM / 32, L / 32, BSZ), 256>>>(x2);

    gemm_proj_x<<<dim3(HDIM / 128, (BSZ * L) / 128), 256, SMEMB>>>(bias);
    gemm_proj_y<<<dim3(HDIM / 128, L / 128, BSZ), 256, SMEMB>>>(bias);
    gemm_scores<<<dim3(L / 128, L / 128, BSZ), 256, SMEMB>>>();
    softmax_kernel<<<BSZ * L, 256>>>();
    gemm_att<<<dim3(HDIM / 128, L / 128, BSZ), 256>>>(x1, out);
}

// round 13
// speedup vs baseline: 3.9048x; 1.0718x over previous
#include <cuda_runtime.h>
#include <cuda_bf16.h>
#include <cuda_fp16.h>
#include <cstdint>

#define BSZ 16
#define L 1024
#define HDIM 768
#define OUTW (4*HDIM)

typedef __nv_bfloat16 bf16;

// ---------------- scratch (device globals; allocation-free rule) ------------
__device__ __align__(256) bf16 g_x1h[(size_t)BSZ*L*HDIM];
__device__ __align__(256) bf16 g_x1l[(size_t)BSZ*L*HDIM];
__device__ __align__(256) bf16 g_x2h[(size_t)BSZ*L*HDIM];   // gathered x2 rows hi (bf16)
__device__ __align__(256) bf16 g_x2l[(size_t)BSZ*L*HDIM];   // gathered x2 rows lo (bf16)
__device__ __align__(256) bf16 g_Wh [(size_t)HDIM*HDIM];
__device__ __align__(256) bf16 g_Wl [(size_t)HDIM*HDIM];
__device__ __align__(256) __half g_xph[(size_t)BSZ*L*HDIM]; // xproj hi (fp16)
__device__ __align__(256) __half g_xpl[(size_t)BSZ*L*HDIM]; // xproj lo (fp16)
__device__ __align__(256) __half g_yph[(size_t)BSZ*L*HDIM]; // yproj hi only (fp16)
__device__ __align__(256) __half g_x2Th[(size_t)BSZ*HDIM*L]; // gathered transpose (fp16)
__device__ __align__(256) __half g_ah [(size_t)BSZ*L*L];     // alpha (compacted cols)
__device__ float g_scores[(size_t)BSZ*L*L];
__device__ int g_cnt[BSZ];
__device__ int g_idx[BSZ][L];

// ---------------- helpers ---------------------------------------------------
__device__ __forceinline__ uint32_t smem_u32(const void* p) {
    uint32_t a;
    asm("{ .reg .u64 t; cvta.to.shared.u64 t, %1; cvt.u32.u64 %0, t; }"
        : "=r"(a) : "l"(p));
    return a;
}
__device__ __forceinline__ void cp16(uint32_t dst, const void* src) {
    asm volatile("cp.async.cg.shared.global [%0], [%1], 16;"
                 :: "r"(dst), "l"(src) : "memory");
}
__device__ __forceinline__ void ldmx4(uint32_t (&r)[4], uint32_t addr) {
    asm volatile("ldmatrix.sync.aligned.m8n8.x4.shared.b16 {%0,%1,%2,%3}, [%4];"
                 : "=r"(r[0]), "=r"(r[1]), "=r"(r[2]), "=r"(r[3]) : "r"(addr));
}
__device__ __forceinline__ void mma16816(float (&c)[4], const uint32_t (&a)[4],
                                         uint32_t b0, uint32_t b1) {
    asm volatile(
        "mma.sync.aligned.m16n8k16.row.col.f32.bf16.bf16.f32 "
        "{%0,%1,%2,%3}, {%4,%5,%6,%7}, {%8,%9}, {%0,%1,%2,%3};"
        : "+f"(c[0]), "+f"(c[1]), "+f"(c[2]), "+f"(c[3])
        : "r"(a[0]), "r"(a[1]), "r"(a[2]), "r"(a[3]), "r"(b0), "r"(b1));
}
__device__ __forceinline__ void mma16816_f16(float (&c)[4], const uint32_t (&a)[4],
                                             uint32_t b0, uint32_t b1) {
    asm volatile(
        "mma.sync.aligned.m16n8k16.row.col.f32.f16.f16.f32 "
        "{%0,%1,%2,%3}, {%4,%5,%6,%7}, {%8,%9}, {%0,%1,%2,%3};"
        : "+f"(c[0]), "+f"(c[1]), "+f"(c[2]), "+f"(c[3])
        : "r"(a[0]), "r"(a[1]), "r"(a[2]), "r"(a[3]), "r"(b0), "r"(b1));
}
__device__ __forceinline__ uint32_t pack_bf(bf16 a, bf16 b) {
    uint16_t ua = *(uint16_t*)&a, ub = *(uint16_t*)&b;
    return (uint32_t)ua | ((uint32_t)ub << 16);
}
__device__ __forceinline__ uint32_t pack_h(__half a, __half b) {
    uint16_t ua = *(uint16_t*)&a, ub = *(uint16_t*)&b;
    return (uint32_t)ua | ((uint32_t)ub << 16);
}
__device__ __forceinline__ void split1(float f, bf16& h, bf16& l) {
    h = __float2bfloat16(f);
    l = __float2bfloat16(f - __bfloat162float(h));
}
__device__ __forceinline__ void split1h(float f, __half& h, __half& l) {
    h = __float2half(f);
    l = __float2half(f - __half2float(h));
}

#define ROWB 80
#define TILEB (128 * ROWB)
#define STAGEB (4 * TILEB)
#define SMEMB (2 * STAGEB)          // 3-pass bf16: 81920
#define STAGEB2 (3 * TILEB)
#define SMEMB2 (2 * STAGEB2)        // 2-pass fp16: 61440
#define STAGEB1 (2 * TILEB)
#define SMEMB1 (2 * STAGEB1)        // 1-pass fp16: 40960 (static)

// ---------------------------------------------------------------------------
// 3-pass split-bf16 mainloop: acc += Ah.Bh^T + Ah.Bl^T + Al.Bh^T
// ---------------------------------------------------------------------------
__device__ __forceinline__ void gemm_core(
    const bf16* __restrict__ Ah, const bf16* __restrict__ Al, int lda,
    const bf16* __restrict__ Bh, const bf16* __restrict__ Bl, int ldb,
    int K, char* smem, float (&acc)[4][4][4])
{
    const int tid  = threadIdx.x;
    const int lane = tid & 31;
    const int wid  = tid >> 5;
    const int wm   = (wid & 1) * 64;
    const int wn   = (wid >> 1) * 32;
    const uint32_t sbase = smem_u32(smem);
    const int nk = K >> 5;

    const int ra = tid >> 2, ca = tid & 3;
    const int rb = ra + 64;

    for (int i = -1; i < nk; ++i) {
        if (i + 1 < nk) {
            const int kt = (i + 1) << 5;
            const uint32_t st = sbase + ((i + 1) & 1) * STAGEB;
            const uint32_t o0 = ra * ROWB + ca * 16;
            const uint32_t o1 = rb * ROWB + ca * 16;
            cp16(st + o0,             Ah + (size_t)ra * lda + kt + ca * 8);
            cp16(st + o1,             Ah + (size_t)rb * lda + kt + ca * 8);
            cp16(st + TILEB + o0,     Al + (size_t)ra * lda + kt + ca * 8);
            cp16(st + TILEB + o1,     Al + (size_t)rb * lda + kt + ca * 8);
            cp16(st + 2*TILEB + o0,   Bh + (size_t)ra * ldb + kt + ca * 8);
            cp16(st + 2*TILEB + o1,   Bh + (size_t)rb * ldb + kt + ca * 8);
            cp16(st + 3*TILEB + o0,   Bl + (size_t)ra * ldb + kt + ca * 8);
            cp16(st + 3*TILEB + o1,   Bl + (size_t)rb * ldb + kt + ca * 8);
            asm volatile("cp.async.commit_group;" ::: "memory");
        }
        if (i < 0) continue;
        if (i + 1 < nk)
            asm volatile("cp.async.wait_group 1;" ::: "memory");
        else
            asm volatile("cp.async.wait_group 0;" ::: "memory");
        __syncthreads();

        const uint32_t sAh = sbase + (i & 1) * STAGEB;
        const uint32_t sAl = sAh + TILEB;
        const uint32_t sBh = sAh + 2 * TILEB;
        const uint32_t sBl = sAh + 3 * TILEB;
        #pragma unroll
        for (int kh = 0; kh < 2; ++kh) {
            const uint32_t coff = (uint32_t)(kh * 2 + (lane >> 4)) * 16;
            const uint32_t brow = (uint32_t)(wn + (lane & 15)) * ROWB + coff;
            uint32_t bh0[4], bh1[4], bl0[4], bl1[4];
            ldmx4(bh0, sBh + brow);
            ldmx4(bh1, sBh + brow + 16u * ROWB);
            ldmx4(bl0, sBl + brow);
            ldmx4(bl1, sBl + brow + 16u * ROWB);
            #pragma unroll
            for (int mi = 0; mi < 4; ++mi) {
                const uint32_t arow = (uint32_t)(wm + mi * 16 + (lane & 15)) * ROWB + coff;
                uint32_t ah[4], al[4];
                ldmx4(ah, sAh + arow);
                ldmx4(al, sAl + arow);
                mma16816(acc[mi][0], ah, bh0[0], bh0[2]);
                mma16816(acc[mi][1], ah, bh0[1], bh0[3]);
                mma16816(acc[mi][2], ah, bh1[0], bh1[2]);
                mma16816(acc[mi][3], ah, bh1[1], bh1[3]);
                mma16816(acc[mi][0], ah, bl0[0], bl0[2]);
                mma16816(acc[mi][1], ah, bl0[1], bl0[3]);
                mma16816(acc[mi][2], ah, bl1[0], bl1[2]);
                mma16816(acc[mi][3], ah, bl1[1], bl1[3]);
                mma16816(acc[mi][0], al, bh0[0], bh0[2]);
                mma16816(acc[mi][1], al, bh0[1], bh0[3]);
                mma16816(acc[mi][2], al, bh1[0], bh1[2]);
                mma16816(acc[mi][3], al, bh1[1], bh1[3]);
            }
        }
        __syncthreads();
    }
}

// ---------------------------------------------------------------------------
// 2-pass fp16 mainloop: acc += (Ah + Al).Bh^T   (A hi/lo fp16, B hi fp16)
// ---------------------------------------------------------------------------
__device__ __forceinline__ void gemm_core_2p(
    const __half* __restrict__ Ah, const __half* __restrict__ Al, int lda,
    const __half* __restrict__ Bh, int ldb,
    int K, char* smem, float (&acc)[4][4][4])
{
    const int tid  = threadIdx.x;
    const int lane = tid & 31;
    const int wid  = tid >> 5;
    const int wm   = (wid & 1) * 64;
    const int wn   = (wid >> 1) * 32;
    const uint32_t sbase = smem_u32(smem);
    const int nk = K >> 5;

    const int ra = tid >> 2, ca = tid & 3;
    const int rb = ra + 64;

    for (int i = -1; i < nk; ++i) {
        if (i + 1 < nk) {
            const int kt = (i + 1) << 5;
            const uint32_t st = sbase + ((i + 1) & 1) * STAGEB2;
            const uint32_t o0 = ra * ROWB + ca * 16;
            const uint32_t o1 = rb * ROWB + ca * 16;
            cp16(st + o0,           Ah + (size_t)ra * lda + kt + ca * 8);
            cp16(st + o1,           Ah + (size_t)rb * lda + kt + ca * 8);
            cp16(st + TILEB + o0,   Al + (size_t)ra * lda + kt + ca * 8);
            cp16(st + TILEB + o1,   Al + (size_t)rb * lda + kt + ca * 8);
            cp16(st + 2*TILEB + o0, Bh + (size_t)ra * ldb + kt + ca * 8);
            cp16(st + 2*TILEB + o1, Bh + (size_t)rb * ldb + kt + ca * 8);
            asm volatile("cp.async.commit_group;" ::: "memory");
        }
        if (i < 0) continue;
        if (i + 1 < nk)
            asm volatile("cp.async.wait_group 1;" ::: "memory");
        else
            asm volatile("cp.async.wait_group 0;" ::: "memory");
        __syncthreads();

        const uint32_t sAh = sbase + (i & 1) * STAGEB2;
        const uint32_t sAl = sAh + TILEB;
        const uint32_t sBh = sAh + 2 * TILEB;
        #pragma unroll
        for (int kh = 0; kh < 2; ++kh) {
            const uint32_t coff = (uint32_t)(kh * 2 + (lane >> 4)) * 16;
            const uint32_t brow = (uint32_t)(wn + (lane & 15)) * ROWB + coff;
            uint32_t bh0[4], bh1[4];
            ldmx4(bh0, sBh + brow);
            ldmx4(bh1, sBh + brow + 16u * ROWB);
            #pragma unroll
            for (int mi = 0; mi < 4; ++mi) {
                const uint32_t arow = (uint32_t)(wm + mi * 16 + (lane & 15)) * ROWB + coff;
                uint32_t ah[4], al[4];
                ldmx4(ah, sAh + arow);
                ldmx4(al, sAl + arow);
                mma16816_f16(acc[mi][0], ah, bh0[0], bh0[2]);
                mma16816_f16(acc[mi][1], ah, bh0[1], bh0[3]);
                mma16816_f16(acc[mi][2], ah, bh1[0], bh1[2]);
                mma16816_f16(acc[mi][3], ah, bh1[1], bh1[3]);
                mma16816_f16(acc[mi][0], al, bh0[0], bh0[2]);
                mma16816_f16(acc[mi][1], al, bh0[1], bh0[3]);
                mma16816_f16(acc[mi][2], al, bh1[0], bh1[2]);
                mma16816_f16(acc[mi][3], al, bh1[1], bh1[3]);
            }
        }
        __syncthreads();
    }
}

// ---------------------------------------------------------------------------
// 1-pass fp16 mainloop: acc += A.B^T
// ---------------------------------------------------------------------------
__device__ __forceinline__ void gemm_core_1p(
    const __half* __restrict__ A, int lda,
    const __half* __restrict__ B, int ldb,
    int K, char* smem, float (&acc)[4][4][4])
{
    const int tid  = threadIdx.x;
    const int lane = tid & 31;
    const int wid  = tid >> 5;
    const int wm   = (wid & 1) * 64;
    const int wn   = (wid >> 1) * 32;
    const uint32_t sbase = smem_u32(smem);
    const int nk = K >> 5;

    const int ra = tid >> 2, ca = tid & 3;
    const int rb = ra + 64;

    for (int i = -1; i < nk; ++i) {
        if (i + 1 < nk) {
            const int kt = (i + 1) << 5;
            const uint32_t st = sbase + ((i + 1) & 1) * STAGEB1;
            const uint32_t o0 = ra * ROWB + ca * 16;
            const uint32_t o1 = rb * ROWB + ca * 16;
            cp16(st + o0,         A + (size_t)ra * lda + kt + ca * 8);
            cp16(st + o1,         A + (size_t)rb * lda + kt + ca * 8);
            cp16(st + TILEB + o0, B + (size_t)ra * ldb + kt + ca * 8);
            cp16(st + TILEB + o1, B + (size_t)rb * ldb + kt + ca * 8);
            asm volatile("cp.async.commit_group;" ::: "memory");
        }
        if (i < 0) continue;
        if (i + 1 < nk)
            asm volatile("cp.async.wait_group 1;" ::: "memory");
        else
            asm volatile("cp.async.wait_group 0;" ::: "memory");
        __syncthreads();

        const uint32_t sA = sbase + (i & 1) * STAGEB1;
        const uint32_t sB = sA + TILEB;
        #pragma unroll
        for (int kh = 0; kh < 2; ++kh) {
            const uint32_t coff = (uint32_t)(kh * 2 + (lane >> 4)) * 16;
            const uint32_t brow = (uint32_t)(wn + (lane & 15)) * ROWB + coff;
            uint32_t bb0[4], bb1[4];
            ldmx4(bb0, sB + brow);
            ldmx4(bb1, sB + brow + 16u * ROWB);
            #pragma unroll
            for (int mi = 0; mi < 4; ++mi) {
                uint32_t aa[4];
                ldmx4(aa, sA + (uint32_t)(wm + mi * 16 + (lane & 15)) * ROWB + coff);
                mma16816_f16(acc[mi][0], aa, bb0[0], bb0[2]);
                mma16816_f16(acc[mi][1], aa, bb0[1], bb0[3]);
                mma16816_f16(acc[mi][2], aa, bb1[0], bb1[2]);
                mma16816_f16(acc[mi][3], aa, bb1[1], bb1[3]);
            }
        }
        __syncthreads();
    }
}

// ---------------------------------------------------------------------------
// Index build: per-batch compacted list of unmasked columns (block scan)
// ---------------------------------------------------------------------------
__global__ __launch_bounds__(256) void index_kernel(const int* __restrict__ x2_mask)
{
    const int b = blockIdx.x, tid = threadIdx.x;
    __shared__ int wsum[8];
    const int* m = x2_mask + (size_t)b * L;
    const int base = tid * 4;
    int keep[4], cnt = 0;
    #pragma unroll
    for (int j = 0; j < 4; ++j) { keep[j] = (m[base + j] == 0); cnt += keep[j]; }
    const int lane = tid & 31, w = tid >> 5;
    int v = cnt;
    #pragma unroll
    for (int o = 1; o < 32; o <<= 1) {
        int t = __shfl_up_sync(0xffffffffu, v, o);
        if (lane >= o) v += t;
    }
    if (lane == 31) wsum[w] = v;
    __syncthreads();
    int woff = 0;
    for (int i = 0; i < w; ++i) woff += wsum[i];
    int pos = woff + v - cnt;   // exclusive prefix
    #pragma unroll
    for (int j = 0; j < 4; ++j)
        if (keep[j]) g_idx[b][pos++] = base + j;
    if (tid == 255) g_cnt[b] = woff + v;
}

// ---------------------------------------------------------------------------
// Split kernels (x1, W)
// ---------------------------------------------------------------------------
__global__ __launch_bounds__(256) void split_kernel(const float* __restrict__ in,
                                                    int which, int n4)
{
    bf16 *hi, *lo;
    if (which == 0) { hi = g_x1h; lo = g_x1l; }
    else            { hi = g_Wh;  lo = g_Wl;  }
    int i = blockIdx.x * 256 + threadIdx.x;
    if (i >= n4) return;
    float4 v = ((const float4*)in)[i];
    bf16 h0, h1, h2, h3, l0, l1, l2, l3;
    split1(v.x, h0, l0); split1(v.y, h1, l1);
    split1(v.z, h2, l2); split1(v.w, h3, l3);
    ((uint2*)hi)[i] = make_uint2(pack_bf(h0, h1), pack_bf(h2, h3));
    ((uint2*)lo)[i] = make_uint2(pack_bf(l0, l1), pack_bf(l2, l3));
}

// ---------------------------------------------------------------------------
// prep_x2: one x2 read -> (a) compacted rows bf16 hi/lo (row-major, zero pad)
//                         (b) compacted transpose fp16.  grid (24, 32, 16)
// ---------------------------------------------------------------------------
__global__ __launch_bounds__(256) void prep_x2(const float* __restrict__ x2)
{
    __shared__ float t[32][33];
    const int b = blockIdx.z;
    const int c = g_cnt[b];
    const int cpad = (c + 127) & ~127;
    const int h0 = blockIdx.x * 32, l0 = blockIdx.y * 32;
    if (l0 >= cpad) return;
    const int tx = threadIdx.x & 31, ty = threadIdx.x >> 5;
    #pragma unroll
    for (int j = 0; j < 4; ++j) {
        const int li = ty + j * 8;
        const int lg = l0 + li;
        float v = 0.f;
        if (lg < c) v = x2[((size_t)b * L + g_idx[b][lg]) * HDIM + h0 + tx];
        t[li][tx] = v;
        bf16 h, l; split1(v, h, l);
        const size_t o = ((size_t)b * L + lg) * HDIM + h0 + tx;
        g_x2h[o] = h;
        g_x2l[o] = l;
    }
    __syncthreads();
    #pragma unroll
    for (int j = 0; j < 4; ++j) {
        const int r = ty + j * 8;   // h-local
        g_x2Th[((size_t)b * HDIM + h0 + r) * L + l0 + tx] = __float2half(t[tx][r]);
    }
}

// ---------------------------------------------------------------------------
// GEMM 1a: xproj = relu(x1 @ W^T + b) -> fp16 hi/lo.  grid (6, 128)
// ---------------------------------------------------------------------------
__global__ __launch_bounds__(256, 2) void gemm_proj_x(const float* __restrict__ bias)
{
    extern __shared__ __align__(128) char gsm[];
    float acc[4][4][4] = {};

    const size_t m0 = (size_t)blockIdx.y * 128;
    const int n0 = blockIdx.x * 128;

    gemm_core(g_x1h + m0 * HDIM, g_x1l + m0 * HDIM, HDIM,
              g_Wh + (size_t)n0 * HDIM, g_Wl + (size_t)n0 * HDIM, HDIM,
              HDIM, gsm, acc);

    const int tid = threadIdx.x, lane = tid & 31, wid = tid >> 5;
    const int wm = (wid & 1) * 64, wn = (wid >> 1) * 32;
    #pragma unroll
    for (int mi = 0; mi < 4; ++mi)
        #pragma unroll
        for (int ni = 0; ni < 4; ++ni)
            #pragma unroll
            for (int h = 0; h < 2; ++h) {
                const size_t m = m0 + wm + mi * 16 + (lane >> 2) + h * 8;
                const int n = n0 + wn + ni * 8 + (lane & 3) * 2;
                float f0 = fmaxf(acc[mi][ni][h * 2]     + bias[n],     0.f);
                float f1 = fmaxf(acc[mi][ni][h * 2 + 1] + bias[n + 1], 0.f);
                __half h0, l0, h1, l1;
                split1h(f0, h0, l0); split1h(f1, h1, l1);
                *(uint32_t*)(g_xph + m * HDIM + n) = pack_h(h0, h1);
                *(uint32_t*)(g_xpl + m * HDIM + n) = pack_h(l0, l1);
            }
}

// ---------------------------------------------------------------------------
// GEMM 1b: yproj over compacted x2 rows -> fp16 hi only. grid (6, 8, 16)
// ---------------------------------------------------------------------------
__global__ __launch_bounds__(256, 2) void gemm_proj_y(const float* __restrict__ bias)
{
    extern __shared__ __align__(128) char gsm[];
    const int b = blockIdx.z;
    const int cpad = (g_cnt[b] + 127) & ~127;
    const size_t m0 = (size_t)blockIdx.y * 128;
    if ((int)m0 >= cpad) return;

    float acc[4][4][4] = {};
    const int n0 = blockIdx.x * 128;
    const size_t boff = (size_t)b * L * HDIM;

    gemm_core(g_x2h + boff + m0 * HDIM, g_x2l + boff + m0 * HDIM, HDIM,
              g_Wh + (size_t)n0 * HDIM, g_Wl + (size_t)n0 * HDIM, HDIM,
              HDIM, gsm, acc);

    const int tid = threadIdx.x, lane = tid & 31, wid = tid >> 5;
    const int wm = (wid & 1) * 64, wn = (wid >> 1) * 32;
    #pragma unroll
    for (int mi = 0; mi < 4; ++mi)
        #pragma unroll
        for (int ni = 0; ni < 4; ++ni)
            #pragma unroll
            for (int h = 0; h < 2; ++h) {
                const size_t m = m0 + wm + mi * 16 + (lane >> 2) + h * 8;
                const int n = n0 + wn + ni * 8 + (lane & 3) * 2;
                float f0 = fmaxf(acc[mi][ni][h * 2]     + bias[n],     0.f);
                float f1 = fmaxf(acc[mi][ni][h * 2 + 1] + bias[n + 1], 0.f);
                *(uint32_t*)(g_yph + boff + m * HDIM + n) =
                    pack_h(__float2half(f0), __float2half(f1));
            }
}

// ---------------------------------------------------------------------------
// GEMM 2: scores = (xh+xl) . yh^T (2-pass fp16), -inf beyond count. grid (8,8,16)
// ---------------------------------------------------------------------------
__global__ __launch_bounds__(256, 2) void gemm_scores()
{
    extern __shared__ __align__(128) char gsm[];
    const int b = blockIdx.z;
    const int c = g_cnt[b];
    const int cpad = (c + 127) & ~127;
    const int n0 = blockIdx.x * 128;
    if (n0 >= cpad) return;

    float acc[4][4][4] = {};
    const size_t m0 = (size_t)blockIdx.y * 128;
    const size_t boff = (size_t)b * L * HDIM;

    gemm_core_2p(g_xph + boff + m0 * HDIM, g_xpl + boff + m0 * HDIM, HDIM,
                 g_yph + boff + (size_t)n0 * HDIM, HDIM,
                 HDIM, gsm, acc);

    const int tid = threadIdx.x, lane = tid & 31, wid = tid >> 5;
    const int wm = (wid & 1) * 64, wn = (wid >> 1) * 32;
    const float NEGINF = __int_as_float(0xff800000u);
    #pragma unroll
    for (int mi = 0; mi < 4; ++mi)
        #pragma unroll
        for (int ni = 0; ni < 4; ++ni)
            #pragma unroll
            for (int h = 0; h < 2; ++h) {
                const size_t m = m0 + wm + mi * 16 + (lane >> 2) + h * 8;
                const int n = n0 + wn + ni * 8 + (lane & 3) * 2;
                float2 o;
                o.x = (n     >= c) ? NEGINF : acc[mi][ni][h * 2];
                o.y = (n + 1 >= c) ? NEGINF : acc[mi][ni][h * 2 + 1];
                *(float2*)(g_scores + ((size_t)b * L + m) * L + n) = o;
            }
}

// ---------------------------------------------------------------------------
// Softmax over compacted cols; fp16 alpha out. grid(16384), 256 threads.
// ---------------------------------------------------------------------------
__global__ __launch_bounds__(256) void softmax_kernel()
{
    const int tid = threadIdx.x;
    const size_t row = blockIdx.x;
    const int b = (int)(row >> 10);
    const int cpad = (g_cnt[b] + 127) & ~127;
    const int col = tid * 4;
    const float NEGINF = __int_as_float(0xff800000u);

    float4 v = make_float4(NEGINF, NEGINF, NEGINF, NEGINF);
    if (col < cpad)
        v = *(((const float4*)g_scores) + row * (L / 4) + tid);

    __shared__ float smax[8];
    __shared__ float ssum[8];

    float m = fmaxf(fmaxf(v.x, v.y), fmaxf(v.z, v.w));
    #pragma unroll
    for (int o = 16; o > 0; o >>= 1)
        m = fmaxf(m, __shfl_xor_sync(0xffffffffu, m, o));
    if ((tid & 31) == 0) smax[tid >> 5] = m;
    __syncthreads();
    m = smax[0];
    #pragma unroll
    for (int w = 1; w < 8; ++w) m = fmaxf(m, smax[w]);

    float4 e;
    e.x = expf(v.x - m); e.y = expf(v.y - m);
    e.z = expf(v.z - m); e.w = expf(v.w - m);
    float s = (e.x + e.y) + (e.z + e.w);
    #pragma unroll
    for (int o = 16; o > 0; o >>= 1)
        s += __shfl_xor_sync(0xffffffffu, s, o);
    if ((tid & 31) == 0) ssum[tid >> 5] = s;
    __syncthreads();
    s = 0.f;
    #pragma unroll
    for (int w = 0; w < 8; ++w) s += ssum[w];

    const float inv = 1.0f / s;
    if (col < cpad) {
        e.x *= inv; e.y *= inv; e.z *= inv; e.w *= inv;
        *(uint2*)(g_ah + row * L + col) = make_uint2(
            pack_h(__float2half(e.x), __float2half(e.y)),
            pack_h(__float2half(e.z), __float2half(e.w)));
    }
}

// ---------------------------------------------------------------------------
// GEMM 3: att = alpha @ x2 over compacted K + concat epilogue. grid (6, 8, 16)
// ---------------------------------------------------------------------------
__global__ __launch_bounds__(256, 2) void gemm_att(const float* __restrict__ x1,
                                                   float* __restrict__ out)
{
    __shared__ __align__(128) char gsm[SMEMB1];
    float acc[4][4][4] = {};

    const int b = blockIdx.z;
    const int cpad = (g_cnt[b] + 127) & ~127;
    const size_t m0 = (size_t)blockIdx.y * 128;
    const int n0 = blockIdx.x * 128;

    gemm_core_1p(g_ah + ((size_t)b * L + m0) * L, L,
                 g_x2Th + ((size_t)b * HDIM + n0) * L, L,
                 cpad, gsm, acc);

    const int tid = threadIdx.x, lane = tid & 31, wid = tid >> 5;
    const int wm = (wid & 1) * 64, wn = (wid >> 1) * 32;
    #pragma unroll
    for (int mi = 0; mi < 4; ++mi)
        #pragma unroll
        for (int ni = 0; ni < 4; ++ni)
            #pragma unroll
            for (int h = 0; h < 2; ++h) {
                const size_t m = m0 + wm + mi * 16 + (lane >> 2) + h * 8;
                const int n = n0 + wn + ni * 8 + (lane & 3) * 2;
                float2 A;
                A.x = acc[mi][ni][h * 2];
                A.y = acc[mi][ni][h * 2 + 1];
                const float* xp = x1 + ((size_t)b * L + m) * HDIM + n;
                float2 xv = *(const float2*)xp;
                float* op = out + ((size_t)b * L + m) * OUTW + n;
                *(float2*)(op)            = xv;
                *(float2*)(op + HDIM)     = A;
                *(float2*)(op + 2 * HDIM) = make_float2(xv.x * A.x, xv.y * A.y);
                *(float2*)(op + 3 * HDIM) = make_float2(xv.x - A.x, xv.y - A.y);
            }
}

// ---------------------------------------------------------------------------
extern "C" void kernel_launch(void* const* d_in, const int* in_sizes, int n_in,
                              void* d_out, int out_size)
{
    const float* x1 = (const float*)d_in[0];
    const float* x2 = (const float*)d_in[1];
    // d_in[2] = x1_mask (unused by reference)
    const int* x2_mask = (const int*)d_in[3];
    const float* W    = (const float*)d_in[4];
    const float* bias = (const float*)d_in[5];
    float* out = (float*)d_out;

    cudaFuncSetAttribute(gemm_proj_x, cudaFuncAttributeMaxDynamicSharedMemorySize, SMEMB);
    cudaFuncSetAttribute(gemm_proj_y, cudaFuncAttributeMaxDynamicSharedMemorySize, SMEMB);
    cudaFuncSetAttribute(gemm_scores, cudaFuncAttributeMaxDynamicSharedMemorySize, SMEMB2);

    const int n4x = BSZ * L * HDIM / 4;
    const int n4w = HDIM * HDIM / 4;

    index_kernel<<<BSZ, 256>>>(x2_mask);
    split_kernel<<<n4x / 256, 256>>>(x1, 0, n4x);
    split_kernel<<<n4w / 256, 256>>>(W, 1, n4w);
    prep_x2<<<dim3(HDIM / 32, L / 32, BSZ), 256>>>(x2);

    gemm_proj_x<<<dim3(HDIM / 128, (BSZ * L) / 128), 256, SMEMB>>>(bias);
    gemm_proj_y<<<dim3(HDIM / 128, L / 128, BSZ), 256, SMEMB>>>(bias);
    gemm_scores<<<dim3(L / 128, L / 128, BSZ), 256, SMEMB2>>>();
    softmax_kernel<<<BSZ * L, 256>>>();
    gemm_att<<<dim3(HDIM / 128, L / 128, BSZ), 256>>>(x1, out);
}